// round 1
// baseline (speedup 1.0000x reference)
#include <cuda_runtime.h>
#include <math.h>

// Problem constants
#define HW     196
#define CDIM   768
#define BATCH  128
#define NHEAD  12
#define HEADS  (BATCH * NHEAD)   // 1536
#define HD     64
#define M_ROWS (BATCH * HW)      // 25088

// Scratch (static __device__ allocations are allowed)
__device__ float g_qkv[(size_t)3 * HEADS * HW * HD];   // [s][head][t][d]
__device__ float g_att[(size_t)M_ROWS * CDIM];         // attention output, pre-proj

// ---------------------------------------------------------------------------
// Tiled fp32 GEMM:  C(MxN) = A(MxK=768) * B(768xN) + bias
// mode 0: A = hidden_states, epilogue scatters into g_qkv with bias
// mode 1: A = g_att,         epilogue writes Cout (d_out) with bias
// ---------------------------------------------------------------------------
constexpr int BM = 128, BN = 128, BK = 16, TM = 8, TN = 8;

__global__ __launch_bounds__(256) void sgemm_kernel(
    const float* __restrict__ A, const float* __restrict__ Bm,
    const float* __restrict__ bias, float* __restrict__ Cout,
    int N, int mode)
{
    const int K = CDIM;
    __shared__ float As[BK][BM];   // transposed: As[k][m]
    __shared__ float Bs[BK][BN];

    int tid = threadIdx.x;
    int tx = tid & 15, ty = tid >> 4;
    int aRow = tid >> 2;           // 0..63 (+64)
    int aCol = (tid & 3) << 2;     // 0,4,8,12
    int bRow = tid >> 5;           // 0..7 (+8)
    int bCol = (tid & 31) << 2;    // 0..124

    const float* Aptr = (mode == 1) ? g_att : A;
    const float* Ablk = Aptr + (size_t)blockIdx.y * BM * K;
    const float* Bblk = Bm + blockIdx.x * BN;

    float acc[TM][TN];
    #pragma unroll
    for (int i = 0; i < TM; i++)
        #pragma unroll
        for (int j = 0; j < TN; j++) acc[i][j] = 0.f;

    for (int k0 = 0; k0 < K; k0 += BK) {
        #pragma unroll
        for (int rr = 0; rr < 2; rr++) {
            int r = aRow + rr * 64;
            float4 v = *(const float4*)(Ablk + (size_t)r * K + k0 + aCol);
            As[aCol + 0][r] = v.x; As[aCol + 1][r] = v.y;
            As[aCol + 2][r] = v.z; As[aCol + 3][r] = v.w;
        }
        #pragma unroll
        for (int rr = 0; rr < 2; rr++) {
            int r = bRow + rr * 8;
            *(float4*)&Bs[r][bCol] = *(const float4*)(Bblk + (size_t)(k0 + r) * N + bCol);
        }
        __syncthreads();
        #pragma unroll
        for (int kk = 0; kk < BK; kk++) {
            float a[TM], b[TN];
            #pragma unroll
            for (int i = 0; i < TM; i++) a[i] = As[kk][ty * TM + i];
            #pragma unroll
            for (int j = 0; j < TN; j++) b[j] = Bs[kk][tx * TN + j];
            #pragma unroll
            for (int i = 0; i < TM; i++)
                #pragma unroll
                for (int j = 0; j < TN; j++)
                    acc[i][j] = fmaf(a[i], b[j], acc[i][j]);
        }
        __syncthreads();
    }

    int mbase = blockIdx.y * BM + ty * TM;
    int nbase = blockIdx.x * BN + tx * TN;

    if (mode == 1) {
        #pragma unroll
        for (int i = 0; i < TM; i++) {
            size_t rowoff = (size_t)(mbase + i) * N;
            #pragma unroll
            for (int j = 0; j < TN; j++)
                Cout[rowoff + nbase + j] = acc[i][j] + bias[nbase + j];
        }
    } else {
        // QKV scatter: col n -> (s = n/768, h = (n%768)/64, d = n%64)
        #pragma unroll
        for (int i = 0; i < TM; i++) {
            int m = mbase + i;
            int bb = m / HW, t = m - bb * HW;
            #pragma unroll
            for (int j = 0; j < TN; j++) {
                int n = nbase + j;
                int s = n / CDIM;
                int rem = n - s * CDIM;
                int h = rem >> 6, d = rem & 63;
                g_qkv[(((size_t)s * HEADS + bb * NHEAD + h) * HW + t) * HD + d]
                    = acc[i][j] + bias[n];
            }
        }
    }
}

// ---------------------------------------------------------------------------
// Fused attention: 1 CTA per (batch, head).
// smem: Q[196][64], K[196][65], V[196][65], relh[196][14], relw[196][14],
//       per-warp P[8][196] (also aliased as rel_pos staging early on)
// ---------------------------------------------------------------------------
constexpr int SQ_OFF   = 0;                  // 196*64 = 12544
constexpr int SK_OFF   = SQ_OFF + 12544;     // 196*65 = 12740
constexpr int SV_OFF   = SK_OFF + 12740;
constexpr int RELH_OFF = SV_OFF + 12740;     // 196*14 = 2744
constexpr int RELW_OFF = RELH_OFF + 2744;
constexpr int SPW_OFF  = RELW_OFF + 2744;    // 8*8*196 = 12544
constexpr int SMEM_FLOATS = SPW_OFF + 12544; // 56056 floats = 224224 B

__global__ __launch_bounds__(256) void attn_kernel(
    const float* __restrict__ rel_h_tab, const float* __restrict__ rel_w_tab)
{
    extern __shared__ float sm[];
    float* sQ   = sm + SQ_OFF;
    float* sK   = sm + SK_OFF;
    float* sV   = sm + SV_OFF;
    float* relh = sm + RELH_OFF;
    float* relw = sm + RELW_OFF;
    float* sPw  = sm + SPW_OFF;

    int head = blockIdx.x;
    int tid  = threadIdx.x;

    const float* qg = g_qkv + (size_t)head * HW * HD;
    const float* kg = qg + (size_t)HEADS * HW * HD;
    const float* vg = kg + (size_t)HEADS * HW * HD;

    for (int idx = tid; idx < HW * HD; idx += 256) {
        int r = idx >> 6, c = idx & 63;
        sQ[idx]          = qg[idx];
        sK[r * 65 + c]   = kg[idx];
        sV[r * 65 + c]   = vg[idx];
    }
    // Stage rel_pos tables in the (currently unused) P buffer: 2*27*64 floats
    float* sRp = sPw;
    for (int idx = tid; idx < 27 * 64; idx += 256) {
        sRp[idx]        = rel_h_tab[idx];
        sRp[1728 + idx] = rel_w_tab[idx];
    }
    __syncthreads();

    // Precompute rel_h[row][kh] and rel_w[row][kw]  (unscaled q, per reference)
    for (int idx = tid; idx < HW * 28; idx += 256) {
        int row = idx / 28, c = idx - row * 28;
        const float* q = sQ + row * 64;
        const float* tab;
        if (c < 14) {
            int ph = row / 14;
            tab = sRp + (ph - c + 13) * 64;
        } else {
            int pw = row % 14;
            tab = sRp + 1728 + (pw - (c - 14) + 13) * 64;
        }
        float s = 0.f;
        #pragma unroll
        for (int u = 0; u < 64; u++) s = fmaf(q[u], tab[u], s);
        if (c < 14) relh[row * 14 + c] = s;
        else        relw[row * 14 + (c - 14)] = s;
    }
    __syncthreads();

    int warp = tid >> 5, lane = tid & 31;
    float* myP = sPw + warp * 8 * HW;
    int bb = head / NHEAD, hh = head - bb * NHEAD;
    float* outp = g_att + (size_t)bb * HW * CDIM + hh * HD;

    const float scale = 0.125f;  // 64^-0.5

    // 25 row-groups of 8 rows (last has 4), distributed over 8 warps
    for (int g = warp; g < 25; g += 8) {
        int row0 = g * 8;
        int rows = min(8, HW - row0);

        // ---- scores: acc[r][i] = q_row . k_j,  j = lane + 32*i ----
        float acc[8][7];
        #pragma unroll
        for (int r = 0; r < 8; r++)
            #pragma unroll
            for (int i = 0; i < 7; i++) acc[r][i] = 0.f;

        for (int c = 0; c < 64; c++) {
            float kreg[7];
            #pragma unroll
            for (int i = 0; i < 7; i++) {
                int j = lane + 32 * i;
                kreg[i] = (j < HW) ? sK[j * 65 + c] : 0.f;
            }
            #pragma unroll
            for (int r = 0; r < 8; r++) {
                float qv = sQ[(row0 + r) * 64 + c];  // OOB rows read junk smem; masked later
                #pragma unroll
                for (int i = 0; i < 7; i++)
                    acc[r][i] = fmaf(qv, kreg[i], acc[r][i]);
            }
        }

        // ---- rel add + softmax per row, write P ----
        for (int r = 0; r < 8; r++) {
            if (r < rows) {
                int row = row0 + r;
                float sc[7];
                float mx = -1e30f;
                #pragma unroll
                for (int i = 0; i < 7; i++) {
                    int j = lane + 32 * i;
                    float s;
                    if (j < HW)
                        s = fmaf(acc[r][i], scale,
                                 relh[row * 14 + j / 14] + relw[row * 14 + (j % 14)]);
                    else
                        s = -1e30f;
                    sc[i] = s;
                    mx = fmaxf(mx, s);
                }
                #pragma unroll
                for (int off = 16; off; off >>= 1)
                    mx = fmaxf(mx, __shfl_xor_sync(0xffffffffu, mx, off));
                float sum = 0.f;
                #pragma unroll
                for (int i = 0; i < 7; i++) {
                    float e = (sc[i] > -1e29f) ? expf(sc[i] - mx) : 0.f;
                    sc[i] = e;
                    sum += e;
                }
                #pragma unroll
                for (int off = 16; off; off >>= 1)
                    sum += __shfl_xor_sync(0xffffffffu, sum, off);
                float inv = 1.f / sum;
                #pragma unroll
                for (int i = 0; i < 7; i++) {
                    int j = lane + 32 * i;
                    if (j < HW) myP[r * HW + j] = sc[i] * inv;
                }
            } else {
                #pragma unroll
                for (int i = 0; i < 7; i++) {
                    int j = lane + 32 * i;
                    if (j < HW) myP[r * HW + j] = 0.f;
                }
            }
        }
        __syncwarp();

        // ---- AV: lane owns output columns d = lane and d = lane+32 ----
        float o0[8], o1[8];
        #pragma unroll
        for (int r = 0; r < 8; r++) { o0[r] = 0.f; o1[r] = 0.f; }

        for (int j0 = 0; j0 < HW; j0 += 4) {
            float v0[4], v1[4];
            #pragma unroll
            for (int qq = 0; qq < 4; qq++) {
                v0[qq] = sV[(j0 + qq) * 65 + lane];
                v1[qq] = sV[(j0 + qq) * 65 + 32 + lane];
            }
            #pragma unroll
            for (int r = 0; r < 8; r++) {
                float4 p = *(const float4*)&myP[r * HW + j0];
                o0[r] = fmaf(p.x, v0[0], fmaf(p.y, v0[1],
                         fmaf(p.z, v0[2], fmaf(p.w, v0[3], o0[r]))));
                o1[r] = fmaf(p.x, v1[0], fmaf(p.y, v1[1],
                         fmaf(p.z, v1[2], fmaf(p.w, v1[3], o1[r]))));
            }
        }
        for (int r = 0; r < rows; r++) {
            int row = row0 + r;
            outp[(size_t)row * CDIM + lane]      = o0[r];
            outp[(size_t)row * CDIM + 32 + lane] = o1[r];
        }
        __syncwarp();
    }
}

// ---------------------------------------------------------------------------
extern "C" void kernel_launch(void* const* d_in, const int* in_sizes, int n_in,
                              void* d_out, int out_size)
{
    const float* hidden = (const float*)d_in[0];
    const float* w_qkv  = (const float*)d_in[1];
    const float* b_qkv  = (const float*)d_in[2];
    const float* rph    = (const float*)d_in[3];
    const float* rpw    = (const float*)d_in[4];
    const float* w_proj = (const float*)d_in[5];
    const float* b_proj = (const float*)d_in[6];
    float* out = (float*)d_out;

    (void)in_sizes; (void)n_in; (void)out_size;

    cudaFuncSetAttribute(attn_kernel, cudaFuncAttributeMaxDynamicSharedMemorySize,
                         SMEM_FLOATS * (int)sizeof(float));

    // 1) QKV GEMM + bias + scatter to per-head q/k/v
    dim3 gq(3 * CDIM / BN, M_ROWS / BM);   // (18, 196)
    sgemm_kernel<<<gq, 256>>>(hidden, w_qkv, b_qkv, nullptr, 3 * CDIM, 0);

    // 2) Fused attention per head (scores + rel pos + softmax + AV)
    attn_kernel<<<HEADS, 256, SMEM_FLOATS * (int)sizeof(float)>>>(rph, rpw);

    // 3) Output projection + bias
    dim3 gp(CDIM / BN, M_ROWS / BM);       // (6, 196)
    sgemm_kernel<<<gp, 256>>>(nullptr, w_proj, b_proj, out, CDIM, 1);
}

// round 2
// speedup vs baseline: 1.7310x; 1.7310x over previous
#include <cuda_runtime.h>
#include <math.h>

// Problem constants
#define HW     196
#define CDIM   768
#define BATCH  128
#define NHEAD  12
#define HEADS  (BATCH * NHEAD)   // 1536
#define HD     64
#define M_ROWS (BATCH * HW)      // 25088

// Scratch
__device__ float g_qkv[(size_t)3 * HEADS * HW * HD];   // [s][head][t][d]
__device__ float g_att[(size_t)M_ROWS * CDIM];         // attention output, pre-proj

__device__ __forceinline__ unsigned f2tf(float x) {
    unsigned r;
    asm("cvt.rna.tf32.f32 %0, %1;" : "=r"(r) : "f"(x));
    return r;
}

__device__ __forceinline__ void mma_tf32(float c[4], const unsigned a[4], const unsigned b[2]) {
    asm volatile(
        "mma.sync.aligned.m16n8k8.row.col.f32.tf32.tf32.f32 "
        "{%0,%1,%2,%3},{%4,%5,%6,%7},{%8,%9},{%0,%1,%2,%3};\n"
        : "+f"(c[0]), "+f"(c[1]), "+f"(c[2]), "+f"(c[3])
        : "r"(a[0]), "r"(a[1]), "r"(a[2]), "r"(a[3]), "r"(b[0]), "r"(b[1]));
}

// ---------------------------------------------------------------------------
// tf32 tensor-core GEMM:  C(MxN) = A(Mx768) * B(768xN) + bias
// mode 0: A = hidden_states, epilogue scatters into g_qkv with bias
// mode 1: A = g_att,         epilogue writes Cout with bias
// Tiles: 128x128x16. 8 warps (4 M x 2 N), warp = 32x64 via m16n8k8.
// ---------------------------------------------------------------------------
constexpr int GBM = 128, GBN = 128, GBK = 16;
constexpr int ASTR = GBK + 4;   // 20  -> A frag banks (20g+t)%32 all distinct
constexpr int BSTR = GBN + 8;   // 136 -> B frag banks (8t+g)   all distinct

__global__ __launch_bounds__(256, 2) void tf32_gemm(
    const float* __restrict__ A, const float* __restrict__ Bm,
    const float* __restrict__ bias, float* __restrict__ Cout,
    int N, int mode)
{
    __shared__ unsigned sA[2][GBM * ASTR];
    __shared__ unsigned sB[2][GBK * BSTR];
    const int K = CDIM;

    int tid = threadIdx.x;
    int warp = tid >> 5, lane = tid & 31;
    int g = lane >> 2, t = lane & 3;
    int wm = warp >> 1, wn = warp & 1;       // 4 x 2 warps
    int rowbase = wm * 32, colbase = wn * 64;

    const float* Aptr = (mode == 1) ? g_att : A;
    const float* Ablk = Aptr + (size_t)blockIdx.y * GBM * K;
    const float* Bblk = Bm + blockIdx.x * GBN;

    float acc[2][8][4];
    #pragma unroll
    for (int mt = 0; mt < 2; mt++)
        #pragma unroll
        for (int nt = 0; nt < 8; nt++)
            #pragma unroll
            for (int r = 0; r < 4; r++) acc[mt][nt][r] = 0.f;

    // Per-thread global-load slots: 2 float4 of A, 2 float4 of B per tile.
    // A: idx -> row = idx>>2, kq = idx&3 (128 rows x 4 float4)
    // B: idx -> row = idx>>5, cq = idx&31 (16 rows x 32 float4)
    float4 ra[2], rb[2];
    int aRow[2], aKq[2], bRow[2], bCq[2];
    #pragma unroll
    for (int u = 0; u < 2; u++) {
        int idx = tid + u * 256;
        aRow[u] = idx >> 2; aKq[u] = idx & 3;
        bRow[u] = idx >> 5; bCq[u] = idx & 31;
    }

    // prologue: tile 0
    #pragma unroll
    for (int u = 0; u < 2; u++) {
        ra[u] = *(const float4*)(Ablk + (size_t)aRow[u] * K + aKq[u] * 4);
        rb[u] = *(const float4*)(Bblk + (size_t)bRow[u] * N + bCq[u] * 4);
    }
    #pragma unroll
    for (int u = 0; u < 2; u++) {
        unsigned* p = &sA[0][aRow[u] * ASTR + aKq[u] * 4];
        p[0] = f2tf(ra[u].x); p[1] = f2tf(ra[u].y); p[2] = f2tf(ra[u].z); p[3] = f2tf(ra[u].w);
        unsigned* q = &sB[0][bRow[u] * BSTR + bCq[u] * 4];
        q[0] = f2tf(rb[u].x); q[1] = f2tf(rb[u].y); q[2] = f2tf(rb[u].z); q[3] = f2tf(rb[u].w);
    }
    __syncthreads();

    const int NT = K / GBK;  // 48
    for (int it = 0; it < NT; it++) {
        int buf = it & 1;
        if (it + 1 < NT) {
            int k0 = (it + 1) * GBK;
            #pragma unroll
            for (int u = 0; u < 2; u++) {
                ra[u] = *(const float4*)(Ablk + (size_t)aRow[u] * K + k0 + aKq[u] * 4);
                rb[u] = *(const float4*)(Bblk + (size_t)(k0 + bRow[u]) * N + bCq[u] * 4);
            }
        }

        #pragma unroll
        for (int kk = 0; kk < 2; kk++) {
            int k = kk * 8;
            unsigned af[2][4], bf[8][2];
            #pragma unroll
            for (int mt = 0; mt < 2; mt++) {
                int r0 = rowbase + mt * 16;
                af[mt][0] = sA[buf][(r0 + g) * ASTR + k + t];
                af[mt][1] = sA[buf][(r0 + g + 8) * ASTR + k + t];
                af[mt][2] = sA[buf][(r0 + g) * ASTR + k + t + 4];
                af[mt][3] = sA[buf][(r0 + g + 8) * ASTR + k + t + 4];
            }
            #pragma unroll
            for (int nt = 0; nt < 8; nt++) {
                int c0 = colbase + nt * 8 + g;
                bf[nt][0] = sB[buf][(k + t) * BSTR + c0];
                bf[nt][1] = sB[buf][(k + t + 4) * BSTR + c0];
            }
            #pragma unroll
            for (int mt = 0; mt < 2; mt++)
                #pragma unroll
                for (int nt = 0; nt < 8; nt++)
                    mma_tf32(acc[mt][nt], af[mt], bf[nt]);
        }
        __syncthreads();

        if (it + 1 < NT) {
            int nb = buf ^ 1;
            #pragma unroll
            for (int u = 0; u < 2; u++) {
                unsigned* p = &sA[nb][aRow[u] * ASTR + aKq[u] * 4];
                p[0] = f2tf(ra[u].x); p[1] = f2tf(ra[u].y); p[2] = f2tf(ra[u].z); p[3] = f2tf(ra[u].w);
                unsigned* q = &sB[nb][bRow[u] * BSTR + bCq[u] * 4];
                q[0] = f2tf(rb[u].x); q[1] = f2tf(rb[u].y); q[2] = f2tf(rb[u].z); q[3] = f2tf(rb[u].w);
            }
            __syncthreads();
        }
    }

    // Epilogue. Fragment c[rh*2+cl]: row = g + rh*8, col = 2t + cl (within 16x8 tile)
    int mrow0 = blockIdx.y * GBM + rowbase;
    int ncol0 = blockIdx.x * GBN + colbase;

    if (mode == 1) {
        #pragma unroll
        for (int mt = 0; mt < 2; mt++)
            #pragma unroll
            for (int nt = 0; nt < 8; nt++)
                #pragma unroll
                for (int rh = 0; rh < 2; rh++)
                    #pragma unroll
                    for (int cl = 0; cl < 2; cl++) {
                        int row = mrow0 + mt * 16 + g + rh * 8;
                        int col = ncol0 + nt * 8 + 2 * t + cl;
                        Cout[(size_t)row * N + col] = acc[mt][nt][rh * 2 + cl] + bias[col];
                    }
    } else {
        // QKV scatter: col n -> (s = n/768, h = (n%768)/64, d = n%64)
        #pragma unroll
        for (int mt = 0; mt < 2; mt++)
            #pragma unroll
            for (int rh = 0; rh < 2; rh++) {
                int m = mrow0 + mt * 16 + g + rh * 8;
                int bb = m / HW, tt = m - bb * HW;
                #pragma unroll
                for (int nt = 0; nt < 8; nt++)
                    #pragma unroll
                    for (int cl = 0; cl < 2; cl++) {
                        int n = ncol0 + nt * 8 + 2 * t + cl;
                        int s = n / CDIM;
                        int rem = n - s * CDIM;
                        int h = rem >> 6, d = rem & 63;
                        g_qkv[(((size_t)s * HEADS + bb * NHEAD + h) * HW + tt) * HD + d]
                            = acc[mt][nt][rh * 2 + cl] + bias[n];
                    }
            }
    }
}

// ---------------------------------------------------------------------------
// Fused attention: 1 CTA per (batch, head). (unchanged from round 1)
// ---------------------------------------------------------------------------
constexpr int SQ_OFF   = 0;                  // 196*64 = 12544
constexpr int SK_OFF   = SQ_OFF + 12544;     // 196*65 = 12740
constexpr int SV_OFF   = SK_OFF + 12740;
constexpr int RELH_OFF = SV_OFF + 12740;     // 196*14 = 2744
constexpr int RELW_OFF = RELH_OFF + 2744;
constexpr int SPW_OFF  = RELW_OFF + 2744;    // 8*8*196 = 12544
constexpr int SMEM_FLOATS = SPW_OFF + 12544; // 56056 floats = 224224 B

__global__ __launch_bounds__(256) void attn_kernel(
    const float* __restrict__ rel_h_tab, const float* __restrict__ rel_w_tab)
{
    extern __shared__ float sm[];
    float* sQ   = sm + SQ_OFF;
    float* sK   = sm + SK_OFF;
    float* sV   = sm + SV_OFF;
    float* relh = sm + RELH_OFF;
    float* relw = sm + RELW_OFF;
    float* sPw  = sm + SPW_OFF;

    int head = blockIdx.x;
    int tid  = threadIdx.x;

    const float* qg = g_qkv + (size_t)head * HW * HD;
    const float* kg = qg + (size_t)HEADS * HW * HD;
    const float* vg = kg + (size_t)HEADS * HW * HD;

    for (int idx = tid; idx < HW * HD; idx += 256) {
        int r = idx >> 6, c = idx & 63;
        sQ[idx]          = qg[idx];
        sK[r * 65 + c]   = kg[idx];
        sV[r * 65 + c]   = vg[idx];
    }
    float* sRp = sPw;
    for (int idx = tid; idx < 27 * 64; idx += 256) {
        sRp[idx]        = rel_h_tab[idx];
        sRp[1728 + idx] = rel_w_tab[idx];
    }
    __syncthreads();

    for (int idx = tid; idx < HW * 28; idx += 256) {
        int row = idx / 28, c = idx - row * 28;
        const float* q = sQ + row * 64;
        const float* tab;
        if (c < 14) {
            int ph = row / 14;
            tab = sRp + (ph - c + 13) * 64;
        } else {
            int pw = row % 14;
            tab = sRp + 1728 + (pw - (c - 14) + 13) * 64;
        }
        float s = 0.f;
        #pragma unroll
        for (int u = 0; u < 64; u++) s = fmaf(q[u], tab[u], s);
        if (c < 14) relh[row * 14 + c] = s;
        else        relw[row * 14 + (c - 14)] = s;
    }
    __syncthreads();

    int warp = tid >> 5, lane = tid & 31;
    float* myP = sPw + warp * 8 * HW;
    int bb = head / NHEAD, hh = head - bb * NHEAD;
    float* outp = g_att + (size_t)bb * HW * CDIM + hh * HD;

    const float scale = 0.125f;

    for (int gidx = warp; gidx < 25; gidx += 8) {
        int row0 = gidx * 8;
        int rows = min(8, HW - row0);

        float acc[8][7];
        #pragma unroll
        for (int r = 0; r < 8; r++)
            #pragma unroll
            for (int i = 0; i < 7; i++) acc[r][i] = 0.f;

        for (int c = 0; c < 64; c++) {
            float kreg[7];
            #pragma unroll
            for (int i = 0; i < 7; i++) {
                int j = lane + 32 * i;
                kreg[i] = (j < HW) ? sK[j * 65 + c] : 0.f;
            }
            #pragma unroll
            for (int r = 0; r < 8; r++) {
                float qv = sQ[(row0 + r) * 64 + c];
                #pragma unroll
                for (int i = 0; i < 7; i++)
                    acc[r][i] = fmaf(qv, kreg[i], acc[r][i]);
            }
        }

        for (int r = 0; r < 8; r++) {
            if (r < rows) {
                int row = row0 + r;
                float sc[7];
                float mx = -1e30f;
                #pragma unroll
                for (int i = 0; i < 7; i++) {
                    int j = lane + 32 * i;
                    float s;
                    if (j < HW)
                        s = fmaf(acc[r][i], scale,
                                 relh[row * 14 + j / 14] + relw[row * 14 + (j % 14)]);
                    else
                        s = -1e30f;
                    sc[i] = s;
                    mx = fmaxf(mx, s);
                }
                #pragma unroll
                for (int off = 16; off; off >>= 1)
                    mx = fmaxf(mx, __shfl_xor_sync(0xffffffffu, mx, off));
                float sum = 0.f;
                #pragma unroll
                for (int i = 0; i < 7; i++) {
                    float e = (sc[i] > -1e29f) ? expf(sc[i] - mx) : 0.f;
                    sc[i] = e;
                    sum += e;
                }
                #pragma unroll
                for (int off = 16; off; off >>= 1)
                    sum += __shfl_xor_sync(0xffffffffu, sum, off);
                float inv = 1.f / sum;
                #pragma unroll
                for (int i = 0; i < 7; i++) {
                    int j = lane + 32 * i;
                    if (j < HW) myP[r * HW + j] = sc[i] * inv;
                }
            } else {
                #pragma unroll
                for (int i = 0; i < 7; i++) {
                    int j = lane + 32 * i;
                    if (j < HW) myP[r * HW + j] = 0.f;
                }
            }
        }
        __syncwarp();

        float o0[8], o1[8];
        #pragma unroll
        for (int r = 0; r < 8; r++) { o0[r] = 0.f; o1[r] = 0.f; }

        for (int j0 = 0; j0 < HW; j0 += 4) {
            float v0[4], v1[4];
            #pragma unroll
            for (int qq = 0; qq < 4; qq++) {
                v0[qq] = sV[(j0 + qq) * 65 + lane];
                v1[qq] = sV[(j0 + qq) * 65 + 32 + lane];
            }
            #pragma unroll
            for (int r = 0; r < 8; r++) {
                float4 p = *(const float4*)&myP[r * HW + j0];
                o0[r] = fmaf(p.x, v0[0], fmaf(p.y, v0[1],
                         fmaf(p.z, v0[2], fmaf(p.w, v0[3], o0[r]))));
                o1[r] = fmaf(p.x, v1[0], fmaf(p.y, v1[1],
                         fmaf(p.z, v1[2], fmaf(p.w, v1[3], o1[r]))));
            }
        }
        for (int r = 0; r < rows; r++) {
            int row = row0 + r;
            outp[(size_t)row * CDIM + lane]      = o0[r];
            outp[(size_t)row * CDIM + 32 + lane] = o1[r];
        }
        __syncwarp();
    }
}

// ---------------------------------------------------------------------------
extern "C" void kernel_launch(void* const* d_in, const int* in_sizes, int n_in,
                              void* d_out, int out_size)
{
    const float* hidden = (const float*)d_in[0];
    const float* w_qkv  = (const float*)d_in[1];
    const float* b_qkv  = (const float*)d_in[2];
    const float* rph    = (const float*)d_in[3];
    const float* rpw    = (const float*)d_in[4];
    const float* w_proj = (const float*)d_in[5];
    const float* b_proj = (const float*)d_in[6];
    float* out = (float*)d_out;

    (void)in_sizes; (void)n_in; (void)out_size;

    cudaFuncSetAttribute(attn_kernel, cudaFuncAttributeMaxDynamicSharedMemorySize,
                         SMEM_FLOATS * (int)sizeof(float));

    // 1) QKV GEMM (tf32 tensor cores) + bias + scatter
    dim3 gq(3 * CDIM / GBN, M_ROWS / GBM);   // (18, 196)
    tf32_gemm<<<gq, 256>>>(hidden, w_qkv, b_qkv, nullptr, 3 * CDIM, 0);

    // 2) Fused attention
    attn_kernel<<<HEADS, 256, SMEM_FLOATS * (int)sizeof(float)>>>(rph, rpw);

    // 3) Output projection (tf32 tensor cores) + bias
    dim3 gp(CDIM / GBN, M_ROWS / GBM);       // (6, 196)
    tf32_gemm<<<gp, 256>>>(nullptr, w_proj, b_proj, out, CDIM, 1);
}

// round 3
// speedup vs baseline: 2.1984x; 1.2700x over previous
#include <cuda_runtime.h>
#include <math.h>

// Problem constants
#define HW     196
#define CDIM   768
#define BATCH  128
#define NHEAD  12
#define HEADS  (BATCH * NHEAD)   // 1536
#define HD     64
#define M_ROWS (BATCH * HW)      // 25088

// Scratch
__device__ float g_qkv[(size_t)3 * HEADS * HW * HD];   // [s][head][t][d]
__device__ float g_att[(size_t)M_ROWS * CDIM];         // attention output, pre-proj

__device__ __forceinline__ unsigned f2tf(float x) {
    unsigned r;
    asm("cvt.rna.tf32.f32 %0, %1;" : "=r"(r) : "f"(x));
    return r;
}

__device__ __forceinline__ void mma_tf32(float c[4], const unsigned a[4], const unsigned b[2]) {
    asm volatile(
        "mma.sync.aligned.m16n8k8.row.col.f32.tf32.tf32.f32 "
        "{%0,%1,%2,%3},{%4,%5,%6,%7},{%8,%9},{%0,%1,%2,%3};\n"
        : "+f"(c[0]), "+f"(c[1]), "+f"(c[2]), "+f"(c[3])
        : "r"(a[0]), "r"(a[1]), "r"(a[2]), "r"(a[3]), "r"(b[0]), "r"(b[1]));
}

// ---------------------------------------------------------------------------
// tf32 tensor-core GEMM:  C(MxN) = A(Mx768) * B(768xN) + bias   (unchanged R2)
// ---------------------------------------------------------------------------
constexpr int GBM = 128, GBN = 128, GBK = 16;
constexpr int ASTR = GBK + 4;
constexpr int BSTR = GBN + 8;

__global__ __launch_bounds__(256, 2) void tf32_gemm(
    const float* __restrict__ A, const float* __restrict__ Bm,
    const float* __restrict__ bias, float* __restrict__ Cout,
    int N, int mode)
{
    __shared__ unsigned sA[2][GBM * ASTR];
    __shared__ unsigned sB[2][GBK * BSTR];
    const int K = CDIM;

    int tid = threadIdx.x;
    int warp = tid >> 5, lane = tid & 31;
    int g = lane >> 2, t = lane & 3;
    int wm = warp >> 1, wn = warp & 1;
    int rowbase = wm * 32, colbase = wn * 64;

    const float* Aptr = (mode == 1) ? g_att : A;
    const float* Ablk = Aptr + (size_t)blockIdx.y * GBM * K;
    const float* Bblk = Bm + blockIdx.x * GBN;

    float acc[2][8][4];
    #pragma unroll
    for (int mt = 0; mt < 2; mt++)
        #pragma unroll
        for (int nt = 0; nt < 8; nt++)
            #pragma unroll
            for (int r = 0; r < 4; r++) acc[mt][nt][r] = 0.f;

    float4 ra[2], rb[2];
    int aRow[2], aKq[2], bRow[2], bCq[2];
    #pragma unroll
    for (int u = 0; u < 2; u++) {
        int idx = tid + u * 256;
        aRow[u] = idx >> 2; aKq[u] = idx & 3;
        bRow[u] = idx >> 5; bCq[u] = idx & 31;
    }

    #pragma unroll
    for (int u = 0; u < 2; u++) {
        ra[u] = *(const float4*)(Ablk + (size_t)aRow[u] * K + aKq[u] * 4);
        rb[u] = *(const float4*)(Bblk + (size_t)bRow[u] * N + bCq[u] * 4);
    }
    #pragma unroll
    for (int u = 0; u < 2; u++) {
        unsigned* p = &sA[0][aRow[u] * ASTR + aKq[u] * 4];
        p[0] = f2tf(ra[u].x); p[1] = f2tf(ra[u].y); p[2] = f2tf(ra[u].z); p[3] = f2tf(ra[u].w);
        unsigned* q = &sB[0][bRow[u] * BSTR + bCq[u] * 4];
        q[0] = f2tf(rb[u].x); q[1] = f2tf(rb[u].y); q[2] = f2tf(rb[u].z); q[3] = f2tf(rb[u].w);
    }
    __syncthreads();

    const int NT = K / GBK;
    for (int it = 0; it < NT; it++) {
        int buf = it & 1;
        if (it + 1 < NT) {
            int k0 = (it + 1) * GBK;
            #pragma unroll
            for (int u = 0; u < 2; u++) {
                ra[u] = *(const float4*)(Ablk + (size_t)aRow[u] * K + k0 + aKq[u] * 4);
                rb[u] = *(const float4*)(Bblk + (size_t)(k0 + bRow[u]) * N + bCq[u] * 4);
            }
        }

        #pragma unroll
        for (int kk = 0; kk < 2; kk++) {
            int k = kk * 8;
            unsigned af[2][4], bf[8][2];
            #pragma unroll
            for (int mt = 0; mt < 2; mt++) {
                int r0 = rowbase + mt * 16;
                af[mt][0] = sA[buf][(r0 + g) * ASTR + k + t];
                af[mt][1] = sA[buf][(r0 + g + 8) * ASTR + k + t];
                af[mt][2] = sA[buf][(r0 + g) * ASTR + k + t + 4];
                af[mt][3] = sA[buf][(r0 + g + 8) * ASTR + k + t + 4];
            }
            #pragma unroll
            for (int nt = 0; nt < 8; nt++) {
                int c0 = colbase + nt * 8 + g;
                bf[nt][0] = sB[buf][(k + t) * BSTR + c0];
                bf[nt][1] = sB[buf][(k + t + 4) * BSTR + c0];
            }
            #pragma unroll
            for (int mt = 0; mt < 2; mt++)
                #pragma unroll
                for (int nt = 0; nt < 8; nt++)
                    mma_tf32(acc[mt][nt], af[mt], bf[nt]);
        }
        __syncthreads();

        if (it + 1 < NT) {
            int nb = buf ^ 1;
            #pragma unroll
            for (int u = 0; u < 2; u++) {
                unsigned* p = &sA[nb][aRow[u] * ASTR + aKq[u] * 4];
                p[0] = f2tf(ra[u].x); p[1] = f2tf(ra[u].y); p[2] = f2tf(ra[u].z); p[3] = f2tf(ra[u].w);
                unsigned* q = &sB[nb][bRow[u] * BSTR + bCq[u] * 4];
                q[0] = f2tf(rb[u].x); q[1] = f2tf(rb[u].y); q[2] = f2tf(rb[u].z); q[3] = f2tf(rb[u].w);
            }
            __syncthreads();
        }
    }

    int mrow0 = blockIdx.y * GBM + rowbase;
    int ncol0 = blockIdx.x * GBN + colbase;

    if (mode == 1) {
        #pragma unroll
        for (int mt = 0; mt < 2; mt++)
            #pragma unroll
            for (int nt = 0; nt < 8; nt++)
                #pragma unroll
                for (int rh = 0; rh < 2; rh++)
                    #pragma unroll
                    for (int cl = 0; cl < 2; cl++) {
                        int row = mrow0 + mt * 16 + g + rh * 8;
                        int col = ncol0 + nt * 8 + 2 * t + cl;
                        Cout[(size_t)row * N + col] = acc[mt][nt][rh * 2 + cl] + bias[col];
                    }
    } else {
        #pragma unroll
        for (int mt = 0; mt < 2; mt++)
            #pragma unroll
            for (int rh = 0; rh < 2; rh++) {
                int m = mrow0 + mt * 16 + g + rh * 8;
                int bb = m / HW, tt = m - bb * HW;
                #pragma unroll
                for (int nt = 0; nt < 8; nt++)
                    #pragma unroll
                    for (int cl = 0; cl < 2; cl++) {
                        int n = ncol0 + nt * 8 + 2 * t + cl;
                        int s = n / CDIM;
                        int rem = n - s * CDIM;
                        int h = rem >> 6, d = rem & 63;
                        g_qkv[(((size_t)s * HEADS + bb * NHEAD + h) * HW + tt) * HD + d]
                            = acc[mt][nt][rh * 2 + cl] + bias[n];
                    }
            }
    }
}

// ---------------------------------------------------------------------------
// Tensor-core attention: 1 CTA per head, mma.m16n8k8.tf32 for QK^T and PV.
// M padded to 208 (13 tiles), processed as block0 = tiles 0..6 (rows 0..111),
// block1 = tiles 7..12 (rows 112..195 + 12 pad rows). Keys padded to 200.
// ---------------------------------------------------------------------------
constexpr int AK_OFF = 0;                    // K tf32: 200 x 68
constexpr int AV_OFF = AK_OFF + 200 * 68;    // V tf32: 200 x 72
constexpr int AS_OFF = AV_OFF + 200 * 72;    // S/P:    112 x 200 (also Q stage)
constexpr int AR_OFF = AS_OFF + 112 * 200;   // rel:    196*14 * 2 (tables staged here)
constexpr int A_SMEM_W = AR_OFF + 5488;      // 55888 words = 223552 B

__global__ __launch_bounds__(256) void attn_tc(
    const float* __restrict__ rel_h_tab, const float* __restrict__ rel_w_tab)
{
    extern __shared__ float sm[];
    unsigned* smu = (unsigned*)sm;
    float* sK  = sm + AK_OFF;   unsigned* sKu = smu + AK_OFF;
    float* sV  = sm + AV_OFF;   unsigned* sVu = smu + AV_OFF;
    float* sS  = sm + AS_OFF;   unsigned* sSu = smu + AS_OFF;
    float* rel = sm + AR_OFF;

    int head = blockIdx.x;
    int tid  = threadIdx.x;
    int warp = tid >> 5, lane = tid & 31;
    int g = lane >> 2, t = lane & 3;

    const float* qg = g_qkv + (size_t)head * HW * HD;
    const float* kg = qg + (size_t)HEADS * HW * HD;
    const float* vg = kg + (size_t)HEADS * HW * HD;

    // ---- Phase 0: loads. Q (fp32) -> sS stage (stride 68); K,V -> tf32 ----
    for (int idx = tid; idx < HW * 16; idx += 256) {   // 196 rows x 16 float4
        int r = idx >> 4, c4 = (idx & 15) << 2;
        float4 q = *(const float4*)(qg + r * 64 + c4);
        float4 k = *(const float4*)(kg + r * 64 + c4);
        float4 v = *(const float4*)(vg + r * 64 + c4);
        float* qs = sS + r * 68 + c4;
        qs[0] = q.x; qs[1] = q.y; qs[2] = q.z; qs[3] = q.w;
        unsigned* ks = sKu + r * 68 + c4;
        ks[0] = f2tf(k.x); ks[1] = f2tf(k.y); ks[2] = f2tf(k.z); ks[3] = f2tf(k.w);
        unsigned* vs = sVu + r * 72 + c4;
        vs[0] = f2tf(v.x); vs[1] = f2tf(v.y); vs[2] = f2tf(v.z); vs[3] = f2tf(v.w);
    }
    // zero V pad rows 196..199 (PV k-padding) and K pad rows (S pad cols)
    for (int idx = tid; idx < 4 * 72; idx += 256) sV[196 * 72 + idx] = 0.f;
    for (int idx = tid; idx < 4 * 68; idx += 256) sK[196 * 68 + idx] = 0.f;
    // stage rel tables (2 x 27 x 64) in rel region
    for (int idx = tid; idx < 1728; idx += 256) {
        rel[idx]        = rel_h_tab[idx];
        rel[1728 + idx] = rel_w_tab[idx];
    }
    __syncthreads();

    // ---- Phase 0b: Q fragment preload (both blocks) + rel compute ----
    unsigned qf[2][8][4];
    #pragma unroll
    for (int b = 0; b < 2; b++) {
        int mt  = (b == 0) ? warp : 7 + warp;
        bool act = (b == 0) ? (warp < 7) : (warp < 6);
        if (act) {
            int r0 = mt * 16;
            #pragma unroll
            for (int ks = 0; ks < 8; ks++) {
                qf[b][ks][0] = f2tf(sS[(r0 + g) * 68 + ks * 8 + t]);
                qf[b][ks][1] = f2tf(sS[(r0 + g + 8) * 68 + ks * 8 + t]);
                qf[b][ks][2] = f2tf(sS[(r0 + g) * 68 + ks * 8 + t + 4]);
                qf[b][ks][3] = f2tf(sS[(r0 + g + 8) * 68 + ks * 8 + t + 4]);
            }
        }
    }
    // rel_h / rel_w dot products (fp32 q), results to regs first
    float rtmp[22];
    #pragma unroll
    for (int u = 0; u < 22; u++) {
        int idx = tid + u * 256;
        if (idx < 5488) {
            int row = idx / 28, c = idx - row * 28;
            const float* q = sS + row * 68;
            const float* tab = (c < 14)
                ? rel + (row / 14 - c + 13) * 64
                : rel + 1728 + (row % 14 - (c - 14) + 13) * 64;
            float s = 0.f;
            #pragma unroll
            for (int d = 0; d < 64; d++) s = fmaf(q[d], tab[d], s);
            rtmp[u] = s;
        }
    }
    __syncthreads();
    #pragma unroll
    for (int u = 0; u < 22; u++) {
        int idx = tid + u * 256;
        if (idx < 5488) {
            int row = idx / 28, c = idx - row * 28;
            if (c < 14) rel[row * 14 + c] = rtmp[u];
            else        rel[2744 + row * 14 + (c - 14)] = rtmp[u];
        }
    }
    // no sync needed before S-phase (disjoint regions); softmax sync covers rel

    int bb = head / NHEAD, hh = head - bb * NHEAD;
    float* outp = g_att + (size_t)bb * HW * CDIM + hh * HD;
    const float scale = 0.125f;

    #pragma unroll
    for (int blk = 0; blk < 2; blk++) {
        int ntiles = (blk == 0) ? 7 : 6;
        bool act = warp < ntiles;
        int mt = blk * 7 + warp;          // global m-tile
        int lr0 = warp * 16;              // local row base in sS

        // ---- S = Q K^T (tiles of 16x8) ----
        if (act) {
            for (int n0 = 0; n0 < 25; n0++) {
                float c4[4] = {0.f, 0.f, 0.f, 0.f};
                #pragma unroll
                for (int ks = 0; ks < 8; ks++) {
                    unsigned bfr[2];
                    bfr[0] = sKu[(n0 * 8 + g) * 68 + ks * 8 + t];
                    bfr[1] = sKu[(n0 * 8 + g) * 68 + ks * 8 + t + 4];
                    mma_tf32(c4, qf[blk][ks], bfr);
                }
                *(float2*)&sS[(lr0 + g) * 200 + n0 * 8 + 2 * t]     = make_float2(c4[0], c4[1]);
                *(float2*)&sS[(lr0 + g + 8) * 200 + n0 * 8 + 2 * t] = make_float2(c4[2], c4[3]);
            }
        }
        __syncthreads();

        // ---- softmax rows (all warps) ----
        int nrows = (blk == 0) ? 112 : 84;     // real rows in this block
        int growb = blk * 112;
        for (int lr = warp; lr < nrows; lr += 8) {
            int grow = growb + lr;
            float vals[7];
            float mx = -1e30f;
            #pragma unroll
            for (int i = 0; i < 7; i++) {
                int j = lane + 32 * i;
                float v;
                if (j < HW)
                    v = fmaf(sS[lr * 200 + j], scale,
                             rel[grow * 14 + j / 14] + rel[2744 + grow * 14 + j % 14]);
                else v = -1e30f;
                vals[i] = v;
                mx = fmaxf(mx, v);
            }
            #pragma unroll
            for (int off = 16; off; off >>= 1)
                mx = fmaxf(mx, __shfl_xor_sync(0xffffffffu, mx, off));
            float sum = 0.f;
            #pragma unroll
            for (int i = 0; i < 7; i++) {
                int j = lane + 32 * i;
                float e = (j < HW) ? __expf(vals[i] - mx) : 0.f;
                vals[i] = e;
                sum += e;
            }
            #pragma unroll
            for (int off = 16; off; off >>= 1)
                sum += __shfl_xor_sync(0xffffffffu, sum, off);
            float inv = 1.f / sum;
            #pragma unroll
            for (int i = 0; i < 7; i++) {
                int j = lane + 32 * i;
                if (j < HW)       sSu[lr * 200 + j] = f2tf(vals[i] * inv);
                else if (j < 200) sSu[lr * 200 + j] = 0u;   // P pad cols
            }
        }
        __syncthreads();

        // ---- O = P V ----
        if (act) {
            float oacc[8][4];
            #pragma unroll
            for (int nt = 0; nt < 8; nt++)
                #pragma unroll
                for (int r = 0; r < 4; r++) oacc[nt][r] = 0.f;

            for (int ks = 0; ks < 25; ks++) {
                unsigned a[4];
                a[0] = sSu[(lr0 + g) * 200 + ks * 8 + t];
                a[1] = sSu[(lr0 + g + 8) * 200 + ks * 8 + t];
                a[2] = sSu[(lr0 + g) * 200 + ks * 8 + t + 4];
                a[3] = sSu[(lr0 + g + 8) * 200 + ks * 8 + t + 4];
                #pragma unroll
                for (int nt = 0; nt < 8; nt++) {
                    unsigned bfr[2];
                    bfr[0] = sVu[(ks * 8 + t) * 72 + nt * 8 + g];
                    bfr[1] = sVu[(ks * 8 + t + 4) * 72 + nt * 8 + g];
                    mma_tf32(oacc[nt], a, bfr);
                }
            }
            // epilogue: rows mt*16 + g (+8), cols nt*8 + 2t (+1)
            #pragma unroll
            for (int rh = 0; rh < 2; rh++) {
                int row = mt * 16 + g + rh * 8;
                if (row < HW) {
                    #pragma unroll
                    for (int nt = 0; nt < 8; nt++) {
                        *(float2*)&outp[(size_t)row * CDIM + nt * 8 + 2 * t] =
                            make_float2(oacc[nt][rh * 2], oacc[nt][rh * 2 + 1]);
                    }
                }
            }
        }
        __syncthreads();   // before block1 overwrites sS
    }
}

// ---------------------------------------------------------------------------
extern "C" void kernel_launch(void* const* d_in, const int* in_sizes, int n_in,
                              void* d_out, int out_size)
{
    const float* hidden = (const float*)d_in[0];
    const float* w_qkv  = (const float*)d_in[1];
    const float* b_qkv  = (const float*)d_in[2];
    const float* rph    = (const float*)d_in[3];
    const float* rpw    = (const float*)d_in[4];
    const float* w_proj = (const float*)d_in[5];
    const float* b_proj = (const float*)d_in[6];
    float* out = (float*)d_out;

    (void)in_sizes; (void)n_in; (void)out_size;

    cudaFuncSetAttribute(attn_tc, cudaFuncAttributeMaxDynamicSharedMemorySize,
                         A_SMEM_W * (int)sizeof(float));

    // 1) QKV GEMM (tf32 tensor cores) + bias + scatter
    dim3 gq(3 * CDIM / GBN, M_ROWS / GBM);   // (18, 196)
    tf32_gemm<<<gq, 256>>>(hidden, w_qkv, b_qkv, nullptr, 3 * CDIM, 0);

    // 2) Tensor-core fused attention
    attn_tc<<<HEADS, 256, A_SMEM_W * (int)sizeof(float)>>>(rph, rpw);

    // 3) Output projection (tf32 tensor cores) + bias
    dim3 gp(CDIM / GBN, M_ROWS / GBM);       // (6, 196)
    tf32_gemm<<<gp, 256>>>(nullptr, w_proj, b_proj, out, CDIM, 1);
}

// round 4
// speedup vs baseline: 2.3853x; 1.0850x over previous
#include <cuda_runtime.h>
#include <math.h>

// Problem constants
#define HW     196
#define CDIM   768
#define BATCH  128
#define NHEAD  12
#define HEADS  (BATCH * NHEAD)   // 1536
#define HD     64
#define M_ROWS (BATCH * HW)      // 25088

// Scratch
__device__ float g_qkv[(size_t)3 * HEADS * HW * HD];   // [s][head][t][d]
__device__ float g_att[(size_t)M_ROWS * CDIM];         // attn out (tf32 bits)
__device__ float g_hid_tf[(size_t)M_ROWS * CDIM];      // hidden, tf32 bits
__device__ float g_wqkv_tf[(size_t)CDIM * 3 * CDIM];   // w_qkv, tf32 bits
__device__ float g_wproj_tf[(size_t)CDIM * CDIM];      // w_proj, tf32 bits

__device__ __forceinline__ unsigned f2tf(float x) {
    unsigned r;
    asm("cvt.rna.tf32.f32 %0, %1;" : "=r"(r) : "f"(x));
    return r;
}

__device__ __forceinline__ void mma_tf32(float c[4], const unsigned a[4], const unsigned b[2]) {
    asm volatile(
        "mma.sync.aligned.m16n8k8.row.col.f32.tf32.tf32.f32 "
        "{%0,%1,%2,%3},{%4,%5,%6,%7},{%8,%9},{%0,%1,%2,%3};\n"
        : "+f"(c[0]), "+f"(c[1]), "+f"(c[2]), "+f"(c[3])
        : "r"(a[0]), "r"(a[1]), "r"(a[2]), "r"(a[3]), "r"(b[0]), "r"(b[1]));
}

__device__ __forceinline__ void cpa16(float* dst, const float* src) {
    unsigned d = (unsigned)__cvta_generic_to_shared(dst);
    asm volatile("cp.async.cg.shared.global [%0], [%1], 16;\n" :: "r"(d), "l"(src));
}
__device__ __forceinline__ void cpa_commit() {
    asm volatile("cp.async.commit_group;\n");
}
template<int N> __device__ __forceinline__ void cpa_wait() {
    asm volatile("cp.async.wait_group %0;\n" :: "n"(N));
}

// ---------------------------------------------------------------------------
// fp32 -> tf32-bits conversion (vectorized)
// ---------------------------------------------------------------------------
__global__ __launch_bounds__(256) void cvt_tf32_kernel(
    const float4* __restrict__ in, float4* __restrict__ out, int n4)
{
    int i = blockIdx.x * 256 + threadIdx.x;
    if (i < n4) {
        float4 v = in[i];
        v.x = __uint_as_float(f2tf(v.x));
        v.y = __uint_as_float(f2tf(v.y));
        v.z = __uint_as_float(f2tf(v.z));
        v.w = __uint_as_float(f2tf(v.w));
        out[i] = v;
    }
}

// ---------------------------------------------------------------------------
// tf32 GEMM with cp.async 3-stage pipeline. Inputs already tf32 bits.
// C(MxN) = A(Mx768) * B(768xN) + bias
// mode 0: A = g_hid_tf, epilogue scatters into g_qkv with bias
// mode 1: A = g_att,    epilogue writes Cout with bias
// ---------------------------------------------------------------------------
constexpr int GBM = 128, GBN = 128, GBK = 16;
constexpr int ASTR = GBK + 4;   // 20
constexpr int BSTR = GBN + 8;   // 136
constexpr int ATILE = GBM * ASTR;  // 2560
constexpr int BTILE = GBK * BSTR;  // 2176
constexpr int GEMM_SMEM_B = 3 * (ATILE + BTILE) * 4;  // 56832 B

__global__ __launch_bounds__(256, 2) void tf32_gemm(
    const float* __restrict__ A, const float* __restrict__ Bm,
    const float* __restrict__ bias, float* __restrict__ Cout,
    int N, int mode)
{
    extern __shared__ float gsm[];
    float* sA = gsm;                      // [3][ATILE]
    float* sB = gsm + 3 * ATILE;          // [3][BTILE]
    const int K = CDIM;

    int tid = threadIdx.x;
    int warp = tid >> 5, lane = tid & 31;
    int g = lane >> 2, t = lane & 3;
    int wm = warp >> 1, wn = warp & 1;
    int rowbase = wm * 32, colbase = wn * 64;

    const float* Ablk = A + (size_t)blockIdx.y * GBM * K;
    const float* Bblk = Bm + blockIdx.x * GBN;

    float acc[2][8][4];
    #pragma unroll
    for (int mt = 0; mt < 2; mt++)
        #pragma unroll
        for (int nt = 0; nt < 8; nt++)
            #pragma unroll
            for (int r = 0; r < 4; r++) acc[mt][nt][r] = 0.f;

    int aRow[2], aKq[2], bRow[2], bCq[2];
    #pragma unroll
    for (int u = 0; u < 2; u++) {
        int idx = tid + u * 256;
        aRow[u] = idx >> 2; aKq[u] = idx & 3;
        bRow[u] = idx >> 5; bCq[u] = idx & 31;
    }

    #define LOAD_STAGE(k0, s)                                                     \
        do {                                                                      \
            _Pragma("unroll")                                                     \
            for (int u = 0; u < 2; u++) {                                         \
                cpa16(sA + (s) * ATILE + aRow[u] * ASTR + aKq[u] * 4,             \
                      Ablk + (size_t)aRow[u] * K + (k0) + aKq[u] * 4);            \
                cpa16(sB + (s) * BTILE + bRow[u] * BSTR + bCq[u] * 4,             \
                      Bblk + (size_t)((k0) + bRow[u]) * N + bCq[u] * 4);          \
            }                                                                     \
        } while (0)

    LOAD_STAGE(0, 0); cpa_commit();
    LOAD_STAGE(GBK, 1); cpa_commit();
    cpa_wait<1>();
    __syncthreads();

    const int NT = K / GBK;  // 48
    for (int it = 0; it < NT; it++) {
        int buf = it % 3;
        if (it + 2 < NT) LOAD_STAGE((it + 2) * GBK, (it + 2) % 3);
        cpa_commit();

        const unsigned* cA = (const unsigned*)(sA + buf * ATILE);
        const unsigned* cB = (const unsigned*)(sB + buf * BTILE);
        #pragma unroll
        for (int kk = 0; kk < 2; kk++) {
            int k = kk * 8;
            unsigned af[2][4], bf[8][2];
            #pragma unroll
            for (int mt = 0; mt < 2; mt++) {
                int r0 = rowbase + mt * 16;
                af[mt][0] = cA[(r0 + g) * ASTR + k + t];
                af[mt][1] = cA[(r0 + g + 8) * ASTR + k + t];
                af[mt][2] = cA[(r0 + g) * ASTR + k + t + 4];
                af[mt][3] = cA[(r0 + g + 8) * ASTR + k + t + 4];
            }
            #pragma unroll
            for (int nt = 0; nt < 8; nt++) {
                int c0 = colbase + nt * 8 + g;
                bf[nt][0] = cB[(k + t) * BSTR + c0];
                bf[nt][1] = cB[(k + t + 4) * BSTR + c0];
            }
            #pragma unroll
            for (int mt = 0; mt < 2; mt++)
                #pragma unroll
                for (int nt = 0; nt < 8; nt++)
                    mma_tf32(acc[mt][nt], af[mt], bf[nt]);
        }

        cpa_wait<1>();
        __syncthreads();
    }

    int mrow0 = blockIdx.y * GBM + rowbase;
    int ncol0 = blockIdx.x * GBN + colbase;

    if (mode == 1) {
        #pragma unroll
        for (int mt = 0; mt < 2; mt++)
            #pragma unroll
            for (int nt = 0; nt < 8; nt++)
                #pragma unroll
                for (int rh = 0; rh < 2; rh++)
                    #pragma unroll
                    for (int cl = 0; cl < 2; cl++) {
                        int row = mrow0 + mt * 16 + g + rh * 8;
                        int col = ncol0 + nt * 8 + 2 * t + cl;
                        Cout[(size_t)row * N + col] = acc[mt][nt][rh * 2 + cl] + bias[col];
                    }
    } else {
        #pragma unroll
        for (int mt = 0; mt < 2; mt++)
            #pragma unroll
            for (int rh = 0; rh < 2; rh++) {
                int m = mrow0 + mt * 16 + g + rh * 8;
                int bb = m / HW, tt = m - bb * HW;
                #pragma unroll
                for (int nt = 0; nt < 8; nt++)
                    #pragma unroll
                    for (int cl = 0; cl < 2; cl++) {
                        int n = ncol0 + nt * 8 + 2 * t + cl;
                        int s = n / CDIM;
                        int rem = n - s * CDIM;
                        int h = rem >> 6, d = rem & 63;
                        g_qkv[(((size_t)s * HEADS + bb * NHEAD + h) * HW + tt) * HD + d]
                            = acc[mt][nt][rh * 2 + cl] + bias[n];
                    }
            }
    }
}

// ---------------------------------------------------------------------------
// Tensor-core attention, 512 threads (16 warps), 1 CTA per head.
// Block0 = m-tiles 0..6 (rows 0..111), block1 = m-tiles 7..12 (rows 112..207).
// S phase: warp (mt, n-half); PV phase: warp (mt, col-half).
// Output written as tf32 bits (consumed by proj GEMM).
// ---------------------------------------------------------------------------
constexpr int AK_OFF = 0;                    // K tf32: 200 x 68
constexpr int AV_OFF = AK_OFF + 200 * 68;    // V tf32: 200 x 72
constexpr int AS_OFF = AV_OFF + 200 * 72;    // S/P: 112 x 200 (Q fp32 stage first)
constexpr int AR_OFF = AS_OFF + 112 * 200;   // rel: tables then results (5488)
constexpr int A_SMEM_W = AR_OFF + 5488;      // 55888 words = 223552 B

__global__ __launch_bounds__(512) void attn_tc(
    const float* __restrict__ rel_h_tab, const float* __restrict__ rel_w_tab)
{
    extern __shared__ float sm[];
    unsigned* smu = (unsigned*)sm;
    float* sK  = sm + AK_OFF;   unsigned* sKu = smu + AK_OFF;
    float* sV  = sm + AV_OFF;   unsigned* sVu = smu + AV_OFF;
    float* sS  = sm + AS_OFF;   unsigned* sSu = smu + AS_OFF;
    float* rel = sm + AR_OFF;

    int head = blockIdx.x;
    int tid  = threadIdx.x;
    int warp = tid >> 5, lane = tid & 31;
    int g = lane >> 2, t = lane & 3;

    const float* qg = g_qkv + (size_t)head * HW * HD;
    const float* kg = qg + (size_t)HEADS * HW * HD;
    const float* vg = kg + (size_t)HEADS * HW * HD;

    // ---- loads: Q fp32 -> sS stage (stride 68); K,V -> tf32 smem ----
    for (int idx = tid; idx < HW * 16; idx += 512) {   // 196 rows x 16 float4
        int r = idx >> 4, c4 = (idx & 15) << 2;
        float4 q = *(const float4*)(qg + r * 64 + c4);
        float4 k = *(const float4*)(kg + r * 64 + c4);
        float4 v = *(const float4*)(vg + r * 64 + c4);
        float* qs = sS + r * 68 + c4;
        qs[0] = q.x; qs[1] = q.y; qs[2] = q.z; qs[3] = q.w;
        unsigned* ks = sKu + r * 68 + c4;
        ks[0] = f2tf(k.x); ks[1] = f2tf(k.y); ks[2] = f2tf(k.z); ks[3] = f2tf(k.w);
        unsigned* vs = sVu + r * 72 + c4;
        vs[0] = f2tf(v.x); vs[1] = f2tf(v.y); vs[2] = f2tf(v.z); vs[3] = f2tf(v.w);
    }
    for (int idx = tid; idx < 4 * 72; idx += 512) sV[196 * 72 + idx] = 0.f;
    for (int idx = tid; idx < 4 * 68; idx += 512) sK[196 * 68 + idx] = 0.f;
    for (int idx = tid; idx < 1728; idx += 512) {
        rel[idx]        = rel_h_tab[idx];
        rel[1728 + idx] = rel_w_tab[idx];
    }
    __syncthreads();

    // ---- rel_h / rel_w dot products (fp32 q), staged through registers ----
    float rtmp[11];
    #pragma unroll
    for (int u = 0; u < 11; u++) {
        int idx = tid + u * 512;
        if (idx < 5488) {
            int row = idx / 28, c = idx - row * 28;
            const float* q = sS + row * 68;
            const float* tab = (c < 14)
                ? rel + (row / 14 - c + 13) * 64
                : rel + 1728 + (row % 14 - (c - 14) + 13) * 64;
            float s = 0.f;
            #pragma unroll
            for (int d = 0; d < 64; d++) s = fmaf(q[d], tab[d], s);
            rtmp[u] = s;
        }
    }
    __syncthreads();
    #pragma unroll
    for (int u = 0; u < 11; u++) {
        int idx = tid + u * 512;
        if (idx < 5488) {
            int row = idx / 28, c = idx - row * 28;
            if (c < 14) rel[row * 14 + c] = rtmp[u];
            else        rel[2744 + row * 14 + (c - 14)] = rtmp[u];
        }
    }
    __syncthreads();

    int bb = head / NHEAD, hh = head - bb * NHEAD;
    float* outp = g_att + (size_t)bb * HW * CDIM + hh * HD;
    const float scale = 0.125f;

    #pragma unroll
    for (int blk = 0; blk < 2; blk++) {
        int ntiles = (blk == 0) ? 7 : 6;
        bool act = (warp >> 1) < ntiles;     // warps 0..13 / 0..11
        int mt  = blk * 7 + (warp >> 1);     // global m-tile
        int lr0 = (warp >> 1) * 16;          // local row base in sS
        int half = warp & 1;

        // Q fragments from gmem (rows beyond 195 read safe garbage; masked later)
        unsigned qf[8][4];
        if (act) {
            int r0 = mt * 16;
            #pragma unroll
            for (int ks = 0; ks < 8; ks++) {
                qf[ks][0] = f2tf(qg[(r0 + g) * 64 + ks * 8 + t]);
                qf[ks][1] = f2tf(qg[(r0 + g + 8) * 64 + ks * 8 + t]);
                qf[ks][2] = f2tf(qg[(r0 + g) * 64 + ks * 8 + t + 4]);
                qf[ks][3] = f2tf(qg[(r0 + g + 8) * 64 + ks * 8 + t + 4]);
            }
        }
        if (blk == 0) __syncthreads();   // Q stage fully read before S overwrites

        // ---- S = Q K^T : warp covers n0 in [13*half, 13*half + 13 - half) ----
        if (act) {
            int n0beg = half * 13, n0end = n0beg + 13 - half;
            for (int n0 = n0beg; n0 < n0end; n0++) {
                float c4[4] = {0.f, 0.f, 0.f, 0.f};
                #pragma unroll
                for (int ks = 0; ks < 8; ks++) {
                    unsigned bfr[2];
                    bfr[0] = sKu[(n0 * 8 + g) * 68 + ks * 8 + t];
                    bfr[1] = sKu[(n0 * 8 + g) * 68 + ks * 8 + t + 4];
                    mma_tf32(c4, qf[ks], bfr);
                }
                *(float2*)&sS[(lr0 + g) * 200 + n0 * 8 + 2 * t]     = make_float2(c4[0], c4[1]);
                *(float2*)&sS[(lr0 + g + 8) * 200 + n0 * 8 + 2 * t] = make_float2(c4[2], c4[3]);
            }
        }
        __syncthreads();

        // ---- softmax rows (16 warps) ----
        int nrows = (blk == 0) ? 112 : 84;
        int growb = blk * 112;
        for (int lr = warp; lr < nrows; lr += 16) {
            int grow = growb + lr;
            float vals[7];
            float mx = -1e30f;
            #pragma unroll
            for (int i = 0; i < 7; i++) {
                int j = lane + 32 * i;
                float v;
                if (j < HW)
                    v = fmaf(sS[lr * 200 + j], scale,
                             rel[grow * 14 + j / 14] + rel[2744 + grow * 14 + j % 14]);
                else v = -1e30f;
                vals[i] = v;
                mx = fmaxf(mx, v);
            }
            #pragma unroll
            for (int off = 16; off; off >>= 1)
                mx = fmaxf(mx, __shfl_xor_sync(0xffffffffu, mx, off));
            float sum = 0.f;
            #pragma unroll
            for (int i = 0; i < 7; i++) {
                int j = lane + 32 * i;
                float e = (j < HW) ? __expf(vals[i] - mx) : 0.f;
                vals[i] = e;
                sum += e;
            }
            #pragma unroll
            for (int off = 16; off; off >>= 1)
                sum += __shfl_xor_sync(0xffffffffu, sum, off);
            float inv = 1.f / sum;
            #pragma unroll
            for (int i = 0; i < 7; i++) {
                int j = lane + 32 * i;
                if (j < HW)       sSu[lr * 200 + j] = f2tf(vals[i] * inv);
                else if (j < 200) sSu[lr * 200 + j] = 0u;
            }
        }
        __syncthreads();

        // ---- O = P V : warp covers nt in [4*half, 4*half+4) ----
        if (act) {
            int ntb = half * 4;
            float oacc[4][4];
            #pragma unroll
            for (int nt = 0; nt < 4; nt++)
                #pragma unroll
                for (int r = 0; r < 4; r++) oacc[nt][r] = 0.f;

            for (int ks = 0; ks < 25; ks++) {
                unsigned a[4];
                a[0] = sSu[(lr0 + g) * 200 + ks * 8 + t];
                a[1] = sSu[(lr0 + g + 8) * 200 + ks * 8 + t];
                a[2] = sSu[(lr0 + g) * 200 + ks * 8 + t + 4];
                a[3] = sSu[(lr0 + g + 8) * 200 + ks * 8 + t + 4];
                #pragma unroll
                for (int nt = 0; nt < 4; nt++) {
                    unsigned bfr[2];
                    bfr[0] = sVu[(ks * 8 + t) * 72 + (ntb + nt) * 8 + g];
                    bfr[1] = sVu[(ks * 8 + t + 4) * 72 + (ntb + nt) * 8 + g];
                    mma_tf32(oacc[nt], a, bfr);
                }
            }
            #pragma unroll
            for (int rh = 0; rh < 2; rh++) {
                int row = mt * 16 + g + rh * 8;
                if (row < HW) {
                    #pragma unroll
                    for (int nt = 0; nt < 4; nt++) {
                        float2 w;
                        w.x = __uint_as_float(f2tf(oacc[nt][rh * 2]));
                        w.y = __uint_as_float(f2tf(oacc[nt][rh * 2 + 1]));
                        *(float2*)&outp[(size_t)row * CDIM + (ntb + nt) * 8 + 2 * t] = w;
                    }
                }
            }
        }
        __syncthreads();
    }
}

// ---------------------------------------------------------------------------
extern "C" void kernel_launch(void* const* d_in, const int* in_sizes, int n_in,
                              void* d_out, int out_size)
{
    const float* hidden = (const float*)d_in[0];
    const float* w_qkv  = (const float*)d_in[1];
    const float* b_qkv  = (const float*)d_in[2];
    const float* rph    = (const float*)d_in[3];
    const float* rpw    = (const float*)d_in[4];
    const float* w_proj = (const float*)d_in[5];
    const float* b_proj = (const float*)d_in[6];
    float* out = (float*)d_out;

    (void)in_sizes; (void)n_in; (void)out_size;

    cudaFuncSetAttribute(attn_tc, cudaFuncAttributeMaxDynamicSharedMemorySize,
                         A_SMEM_W * (int)sizeof(float));
    cudaFuncSetAttribute(tf32_gemm, cudaFuncAttributeMaxDynamicSharedMemorySize,
                         GEMM_SMEM_B);

    float *p_hid_tf, *p_wqkv_tf, *p_wproj_tf;
    cudaGetSymbolAddress((void**)&p_hid_tf,   g_hid_tf);
    cudaGetSymbolAddress((void**)&p_wqkv_tf,  g_wqkv_tf);
    cudaGetSymbolAddress((void**)&p_wproj_tf, g_wproj_tf);

    // 0) pre-convert GEMM inputs to tf32 bits
    int n4h = M_ROWS * CDIM / 4;
    int n4q = CDIM * 3 * CDIM / 4;
    int n4p = CDIM * CDIM / 4;
    cvt_tf32_kernel<<<(n4h + 255) / 256, 256>>>((const float4*)hidden, (float4*)p_hid_tf, n4h);
    cvt_tf32_kernel<<<(n4q + 255) / 256, 256>>>((const float4*)w_qkv, (float4*)p_wqkv_tf, n4q);
    cvt_tf32_kernel<<<(n4p + 255) / 256, 256>>>((const float4*)w_proj, (float4*)p_wproj_tf, n4p);

    // 1) QKV GEMM + bias + scatter
    dim3 gq(3 * CDIM / GBN, M_ROWS / GBM);   // (18, 196)
    tf32_gemm<<<gq, 256, GEMM_SMEM_B>>>(p_hid_tf, p_wqkv_tf, b_qkv, nullptr, 3 * CDIM, 0);

    // 2) Tensor-core fused attention (writes g_att as tf32 bits)
    attn_tc<<<HEADS, 512, A_SMEM_W * (int)sizeof(float)>>>(rph, rpw);

    // 3) Output projection + bias
    float* p_att;
    cudaGetSymbolAddress((void**)&p_att, g_att);
    dim3 gp(CDIM / GBN, M_ROWS / GBM);       // (6, 196)
    tf32_gemm<<<gp, 256, GEMM_SMEM_B>>>(p_att, p_wproj_tf, b_proj, out, CDIM, 1);
}

// round 5
// speedup vs baseline: 3.2615x; 1.3673x over previous
#include <cuda_runtime.h>
#include <math.h>

// Problem constants
#define HW     196
#define CDIM   768
#define BATCH  128
#define NHEAD  12
#define HEADS  (BATCH * NHEAD)   // 1536
#define HD     64
#define M_ROWS (BATCH * HW)      // 25088

// Scratch
__device__ float g_qkv[(size_t)3 * HEADS * HW * HD];   // [s][head][t][d]
__device__ float g_att[(size_t)M_ROWS * CDIM];         // attn out (tf32 bits)
__device__ float g_hid_tf[(size_t)M_ROWS * CDIM];      // hidden, tf32 bits
__device__ float g_wqkv_tf[(size_t)CDIM * 3 * CDIM];   // w_qkv, tf32 bits
__device__ float g_wproj_tf[(size_t)CDIM * CDIM];      // w_proj, tf32 bits

__device__ __forceinline__ unsigned f2tf(float x) {
    unsigned r;
    asm("cvt.rna.tf32.f32 %0, %1;" : "=r"(r) : "f"(x));
    return r;
}

__device__ __forceinline__ void mma_tf32(float c[4], const unsigned a[4], const unsigned b[2]) {
    asm volatile(
        "mma.sync.aligned.m16n8k8.row.col.f32.tf32.tf32.f32 "
        "{%0,%1,%2,%3},{%4,%5,%6,%7},{%8,%9},{%0,%1,%2,%3};\n"
        : "+f"(c[0]), "+f"(c[1]), "+f"(c[2]), "+f"(c[3])
        : "r"(a[0]), "r"(a[1]), "r"(a[2]), "r"(a[3]), "r"(b[0]), "r"(b[1]));
}

__device__ __forceinline__ void cpa16(float* dst, const float* src) {
    unsigned d = (unsigned)__cvta_generic_to_shared(dst);
    asm volatile("cp.async.cg.shared.global [%0], [%1], 16;\n" :: "r"(d), "l"(src));
}
__device__ __forceinline__ void cpa_commit() {
    asm volatile("cp.async.commit_group;\n");
}
template<int N> __device__ __forceinline__ void cpa_wait() {
    asm volatile("cp.async.wait_group %0;\n" :: "n"(N));
}

// ---------------------------------------------------------------------------
// fp32 -> tf32-bits conversion (vectorized)
// ---------------------------------------------------------------------------
__global__ __launch_bounds__(256) void cvt_tf32_kernel(
    const float4* __restrict__ in, float4* __restrict__ out, int n4)
{
    int i = blockIdx.x * 256 + threadIdx.x;
    if (i < n4) {
        float4 v = in[i];
        v.x = __uint_as_float(f2tf(v.x));
        v.y = __uint_as_float(f2tf(v.y));
        v.z = __uint_as_float(f2tf(v.z));
        v.w = __uint_as_float(f2tf(v.w));
        out[i] = v;
    }
}

// ---------------------------------------------------------------------------
// tf32 GEMM with cp.async 3-stage pipeline. Inputs already tf32 bits.
// ---------------------------------------------------------------------------
constexpr int GBM = 128, GBN = 128, GBK = 16;
constexpr int ASTR = GBK + 4;   // 20
constexpr int BSTR = GBN + 8;   // 136
constexpr int ATILE = GBM * ASTR;  // 2560
constexpr int BTILE = GBK * BSTR;  // 2176
constexpr int GEMM_SMEM_B = 3 * (ATILE + BTILE) * 4;  // 56832 B

__global__ __launch_bounds__(256, 2) void tf32_gemm(
    const float* __restrict__ A, const float* __restrict__ Bm,
    const float* __restrict__ bias, float* __restrict__ Cout,
    int N, int mode)
{
    extern __shared__ float gsm[];
    float* sA = gsm;                      // [3][ATILE]
    float* sB = gsm + 3 * ATILE;          // [3][BTILE]
    const int K = CDIM;

    int tid = threadIdx.x;
    int warp = tid >> 5, lane = tid & 31;
    int g = lane >> 2, t = lane & 3;
    int wm = warp >> 1, wn = warp & 1;
    int rowbase = wm * 32, colbase = wn * 64;

    const float* Ablk = A + (size_t)blockIdx.y * GBM * K;
    const float* Bblk = Bm + blockIdx.x * GBN;

    float acc[2][8][4];
    #pragma unroll
    for (int mt = 0; mt < 2; mt++)
        #pragma unroll
        for (int nt = 0; nt < 8; nt++)
            #pragma unroll
            for (int r = 0; r < 4; r++) acc[mt][nt][r] = 0.f;

    int aRow[2], aKq[2], bRow[2], bCq[2];
    #pragma unroll
    for (int u = 0; u < 2; u++) {
        int idx = tid + u * 256;
        aRow[u] = idx >> 2; aKq[u] = idx & 3;
        bRow[u] = idx >> 5; bCq[u] = idx & 31;
    }

    #define LOAD_STAGE(k0, s)                                                     \
        do {                                                                      \
            _Pragma("unroll")                                                     \
            for (int u = 0; u < 2; u++) {                                         \
                cpa16(sA + (s) * ATILE + aRow[u] * ASTR + aKq[u] * 4,             \
                      Ablk + (size_t)aRow[u] * K + (k0) + aKq[u] * 4);            \
                cpa16(sB + (s) * BTILE + bRow[u] * BSTR + bCq[u] * 4,             \
                      Bblk + (size_t)((k0) + bRow[u]) * N + bCq[u] * 4);          \
            }                                                                     \
        } while (0)

    LOAD_STAGE(0, 0); cpa_commit();
    LOAD_STAGE(GBK, 1); cpa_commit();
    cpa_wait<1>();
    __syncthreads();

    const int NT = K / GBK;  // 48
    for (int it = 0; it < NT; it++) {
        int buf = it % 3;
        if (it + 2 < NT) LOAD_STAGE((it + 2) * GBK, (it + 2) % 3);
        cpa_commit();

        const unsigned* cA = (const unsigned*)(sA + buf * ATILE);
        const unsigned* cB = (const unsigned*)(sB + buf * BTILE);
        #pragma unroll
        for (int kk = 0; kk < 2; kk++) {
            int k = kk * 8;
            unsigned af[2][4], bf[8][2];
            #pragma unroll
            for (int mt = 0; mt < 2; mt++) {
                int r0 = rowbase + mt * 16;
                af[mt][0] = cA[(r0 + g) * ASTR + k + t];
                af[mt][1] = cA[(r0 + g + 8) * ASTR + k + t];
                af[mt][2] = cA[(r0 + g) * ASTR + k + t + 4];
                af[mt][3] = cA[(r0 + g + 8) * ASTR + k + t + 4];
            }
            #pragma unroll
            for (int nt = 0; nt < 8; nt++) {
                int c0 = colbase + nt * 8 + g;
                bf[nt][0] = cB[(k + t) * BSTR + c0];
                bf[nt][1] = cB[(k + t + 4) * BSTR + c0];
            }
            #pragma unroll
            for (int mt = 0; mt < 2; mt++)
                #pragma unroll
                for (int nt = 0; nt < 8; nt++)
                    mma_tf32(acc[mt][nt], af[mt], bf[nt]);
        }

        cpa_wait<1>();
        __syncthreads();
    }

    int mrow0 = blockIdx.y * GBM + rowbase;
    int ncol0 = blockIdx.x * GBN + colbase;

    if (mode == 1) {
        #pragma unroll
        for (int mt = 0; mt < 2; mt++)
            #pragma unroll
            for (int nt = 0; nt < 8; nt++)
                #pragma unroll
                for (int rh = 0; rh < 2; rh++)
                    #pragma unroll
                    for (int cl = 0; cl < 2; cl++) {
                        int row = mrow0 + mt * 16 + g + rh * 8;
                        int col = ncol0 + nt * 8 + 2 * t + cl;
                        Cout[(size_t)row * N + col] = acc[mt][nt][rh * 2 + cl] + bias[col];
                    }
    } else {
        #pragma unroll
        for (int mt = 0; mt < 2; mt++)
            #pragma unroll
            for (int rh = 0; rh < 2; rh++) {
                int m = mrow0 + mt * 16 + g + rh * 8;
                int bb = m / HW, tt = m - bb * HW;
                #pragma unroll
                for (int nt = 0; nt < 8; nt++)
                    #pragma unroll
                    for (int cl = 0; cl < 2; cl++) {
                        int n = ncol0 + nt * 8 + 2 * t + cl;
                        int s = n / CDIM;
                        int rem = n - s * CDIM;
                        int h = rem >> 6, d = rem & 63;
                        g_qkv[(((size_t)s * HEADS + bb * NHEAD + h) * HW + tt) * HD + d]
                            = acc[mt][nt][rh * 2 + cl] + bias[n];
                    }
            }
    }
}

// ---------------------------------------------------------------------------
// Tensor-core attention, 512 threads, 1 CTA per head.
// rel-pos logits computed via MMA: G = Q @ [TabH|TabW]^T (no bank-conflicted
// scalar dots). G stored in the S buffer (stride 58), gathered into rel.
// ---------------------------------------------------------------------------
constexpr int AK_OFF = 0;                    // K tf32: 200 x 68
constexpr int AV_OFF = AK_OFF + 200 * 68;    // V tf32: 200 x 72
constexpr int AS_OFF = AV_OFF + 200 * 72;    // S/P: 112 x 200 (G stage first: 208 x 58)
constexpr int AR_OFF = AS_OFF + 112 * 200;   // rel: 5488 (Tab stage 56x68=3808 first)
constexpr int A_SMEM_W = AR_OFF + 5488;      // 55888 words = 223552 B
constexpr int GSTR = 58;                     // G row stride

__global__ __launch_bounds__(512) void attn_tc(
    const float* __restrict__ rel_h_tab, const float* __restrict__ rel_w_tab)
{
    extern __shared__ float sm[];
    unsigned* smu = (unsigned*)sm;
    float* sK  = sm + AK_OFF;   unsigned* sKu = smu + AK_OFF;
    float* sV  = sm + AV_OFF;   unsigned* sVu = smu + AV_OFF;
    float* sS  = sm + AS_OFF;   unsigned* sSu = smu + AS_OFF;
    float* rel = sm + AR_OFF;   unsigned* sTb = smu + AR_OFF;   // Tab stage (tf32)

    int head = blockIdx.x;
    int tid  = threadIdx.x;
    int warp = tid >> 5, lane = tid & 31;
    int g = lane >> 2, t = lane & 3;

    const float* qg = g_qkv + (size_t)head * HW * HD;
    const float* kg = qg + (size_t)HEADS * HW * HD;
    const float* vg = kg + (size_t)HEADS * HW * HD;

    // ---- loads: K,V -> tf32 smem; Tab (H|W|pad) -> tf32, stride 68 ----
    for (int idx = tid; idx < HW * 16; idx += 512) {   // 196 rows x 16 float4
        int r = idx >> 4, c4 = (idx & 15) << 2;
        float4 k = *(const float4*)(kg + r * 64 + c4);
        float4 v = *(const float4*)(vg + r * 64 + c4);
        unsigned* ks = sKu + r * 68 + c4;
        ks[0] = f2tf(k.x); ks[1] = f2tf(k.y); ks[2] = f2tf(k.z); ks[3] = f2tf(k.w);
        unsigned* vs = sVu + r * 72 + c4;
        vs[0] = f2tf(v.x); vs[1] = f2tf(v.y); vs[2] = f2tf(v.z); vs[3] = f2tf(v.w);
    }
    for (int idx = tid; idx < 4 * 72; idx += 512) sV[196 * 72 + idx] = 0.f;
    for (int idx = tid; idx < 4 * 68; idx += 512) sK[196 * 68 + idx] = 0.f;
    for (int idx = tid; idx < 56 * 64; idx += 512) {
        int j = idx >> 6, d = idx & 63;
        float v = (j < 27) ? rel_h_tab[j * 64 + d]
                 : (j < 54) ? rel_w_tab[(j - 27) * 64 + d] : 0.f;
        sTb[j * 68 + d] = f2tf(v);
    }
    __syncthreads();

    // ---- G = Q @ Tab^T  (warps 0..12, one 16-row tile each) ----
    if (warp < 13) {
        int r0 = warp * 16;
        unsigned qf[8][4];
        #pragma unroll
        for (int ks = 0; ks < 8; ks++) {
            qf[ks][0] = f2tf(qg[(r0 + g) * 64 + ks * 8 + t]);
            qf[ks][1] = f2tf(qg[(r0 + g + 8) * 64 + ks * 8 + t]);
            qf[ks][2] = f2tf(qg[(r0 + g) * 64 + ks * 8 + t + 4]);
            qf[ks][3] = f2tf(qg[(r0 + g + 8) * 64 + ks * 8 + t + 4]);
        }
        #pragma unroll
        for (int n0 = 0; n0 < 7; n0++) {
            float c4[4] = {0.f, 0.f, 0.f, 0.f};
            #pragma unroll
            for (int ks = 0; ks < 8; ks++) {
                unsigned bfr[2];
                bfr[0] = sTb[(n0 * 8 + g) * 68 + ks * 8 + t];
                bfr[1] = sTb[(n0 * 8 + g) * 68 + ks * 8 + t + 4];
                mma_tf32(c4, qf[ks], bfr);
            }
            *(float2*)&sS[(r0 + g) * GSTR + n0 * 8 + 2 * t]     = make_float2(c4[0], c4[1]);
            *(float2*)&sS[(r0 + g + 8) * GSTR + n0 * 8 + 2 * t] = make_float2(c4[2], c4[3]);
        }
    }
    __syncthreads();

    // ---- gather G -> rel_h / rel_w (overwrites Tab stage; G is in sS) ----
    for (int idx = tid; idx < 5488; idx += 512) {
        int row = idx / 28, c = idx - row * 28;
        if (c < 14)
            rel[row * 14 + c] = sS[row * GSTR + (row / 14 - c + 13)];
        else
            rel[2744 + row * 14 + (c - 14)] = sS[row * GSTR + 27 + (row % 14) - (c - 14) + 13];
    }
    __syncthreads();

    int bb = head / NHEAD, hh = head - bb * NHEAD;
    float* outp = g_att + (size_t)bb * HW * CDIM + hh * HD;
    const float scale = 0.125f;

    #pragma unroll
    for (int blk = 0; blk < 2; blk++) {
        int ntiles = (blk == 0) ? 7 : 6;
        bool act = (warp >> 1) < ntiles;     // warps 0..13 / 0..11
        int mt  = blk * 7 + (warp >> 1);     // global m-tile
        int lr0 = (warp >> 1) * 16;          // local row base in sS
        int half = warp & 1;

        // Q fragments from gmem (rows beyond 195 read safe in-plane garbage)
        unsigned qf[8][4];
        if (act) {
            int r0 = mt * 16;
            #pragma unroll
            for (int ks = 0; ks < 8; ks++) {
                qf[ks][0] = f2tf(qg[(r0 + g) * 64 + ks * 8 + t]);
                qf[ks][1] = f2tf(qg[(r0 + g + 8) * 64 + ks * 8 + t]);
                qf[ks][2] = f2tf(qg[(r0 + g) * 64 + ks * 8 + t + 4]);
                qf[ks][3] = f2tf(qg[(r0 + g + 8) * 64 + ks * 8 + t + 4]);
            }
        }

        // ---- S = Q K^T : warp covers n0 in [13*half, 13*half + 13 - half) ----
        if (act) {
            int n0beg = half * 13, n0end = n0beg + 13 - half;
            for (int n0 = n0beg; n0 < n0end; n0++) {
                float c4[4] = {0.f, 0.f, 0.f, 0.f};
                #pragma unroll
                for (int ks = 0; ks < 8; ks++) {
                    unsigned bfr[2];
                    bfr[0] = sKu[(n0 * 8 + g) * 68 + ks * 8 + t];
                    bfr[1] = sKu[(n0 * 8 + g) * 68 + ks * 8 + t + 4];
                    mma_tf32(c4, qf[ks], bfr);
                }
                *(float2*)&sS[(lr0 + g) * 200 + n0 * 8 + 2 * t]     = make_float2(c4[0], c4[1]);
                *(float2*)&sS[(lr0 + g + 8) * 200 + n0 * 8 + 2 * t] = make_float2(c4[2], c4[3]);
            }
        }
        __syncthreads();

        // ---- softmax rows (16 warps) ----
        int nrows = (blk == 0) ? 112 : 84;
        int growb = blk * 112;
        for (int lr = warp; lr < nrows; lr += 16) {
            int grow = growb + lr;
            float vals[7];
            float mx = -1e30f;
            #pragma unroll
            for (int i = 0; i < 7; i++) {
                int j = lane + 32 * i;
                float v;
                if (j < HW)
                    v = fmaf(sS[lr * 200 + j], scale,
                             rel[grow * 14 + j / 14] + rel[2744 + grow * 14 + j % 14]);
                else v = -1e30f;
                vals[i] = v;
                mx = fmaxf(mx, v);
            }
            #pragma unroll
            for (int off = 16; off; off >>= 1)
                mx = fmaxf(mx, __shfl_xor_sync(0xffffffffu, mx, off));
            float sum = 0.f;
            #pragma unroll
            for (int i = 0; i < 7; i++) {
                int j = lane + 32 * i;
                float e = (j < HW) ? __expf(vals[i] - mx) : 0.f;
                vals[i] = e;
                sum += e;
            }
            #pragma unroll
            for (int off = 16; off; off >>= 1)
                sum += __shfl_xor_sync(0xffffffffu, sum, off);
            float inv = 1.f / sum;
            #pragma unroll
            for (int i = 0; i < 7; i++) {
                int j = lane + 32 * i;
                if (j < HW)       sSu[lr * 200 + j] = f2tf(vals[i] * inv);
                else if (j < 200) sSu[lr * 200 + j] = 0u;
            }
        }
        __syncthreads();

        // ---- O = P V : warp covers nt in [4*half, 4*half+4) ----
        if (act) {
            int ntb = half * 4;
            float oacc[4][4];
            #pragma unroll
            for (int nt = 0; nt < 4; nt++)
                #pragma unroll
                for (int r = 0; r < 4; r++) oacc[nt][r] = 0.f;

            for (int ks = 0; ks < 25; ks++) {
                unsigned a[4];
                a[0] = sSu[(lr0 + g) * 200 + ks * 8 + t];
                a[1] = sSu[(lr0 + g + 8) * 200 + ks * 8 + t];
                a[2] = sSu[(lr0 + g) * 200 + ks * 8 + t + 4];
                a[3] = sSu[(lr0 + g + 8) * 200 + ks * 8 + t + 4];
                #pragma unroll
                for (int nt = 0; nt < 4; nt++) {
                    unsigned bfr[2];
                    bfr[0] = sVu[(ks * 8 + t) * 72 + (ntb + nt) * 8 + g];
                    bfr[1] = sVu[(ks * 8 + t + 4) * 72 + (ntb + nt) * 8 + g];
                    mma_tf32(oacc[nt], a, bfr);
                }
            }
            #pragma unroll
            for (int rh = 0; rh < 2; rh++) {
                int row = mt * 16 + g + rh * 8;
                if (row < HW) {
                    #pragma unroll
                    for (int nt = 0; nt < 4; nt++) {
                        float2 w;
                        w.x = __uint_as_float(f2tf(oacc[nt][rh * 2]));
                        w.y = __uint_as_float(f2tf(oacc[nt][rh * 2 + 1]));
                        *(float2*)&outp[(size_t)row * CDIM + (ntb + nt) * 8 + 2 * t] = w;
                    }
                }
            }
        }
        __syncthreads();
    }
}

// ---------------------------------------------------------------------------
extern "C" void kernel_launch(void* const* d_in, const int* in_sizes, int n_in,
                              void* d_out, int out_size)
{
    const float* hidden = (const float*)d_in[0];
    const float* w_qkv  = (const float*)d_in[1];
    const float* b_qkv  = (const float*)d_in[2];
    const float* rph    = (const float*)d_in[3];
    const float* rpw    = (const float*)d_in[4];
    const float* w_proj = (const float*)d_in[5];
    const float* b_proj = (const float*)d_in[6];
    float* out = (float*)d_out;

    (void)in_sizes; (void)n_in; (void)out_size;

    cudaFuncSetAttribute(attn_tc, cudaFuncAttributeMaxDynamicSharedMemorySize,
                         A_SMEM_W * (int)sizeof(float));
    cudaFuncSetAttribute(tf32_gemm, cudaFuncAttributeMaxDynamicSharedMemorySize,
                         GEMM_SMEM_B);

    float *p_hid_tf, *p_wqkv_tf, *p_wproj_tf;
    cudaGetSymbolAddress((void**)&p_hid_tf,   g_hid_tf);
    cudaGetSymbolAddress((void**)&p_wqkv_tf,  g_wqkv_tf);
    cudaGetSymbolAddress((void**)&p_wproj_tf, g_wproj_tf);

    // 0) pre-convert GEMM inputs to tf32 bits
    int n4h = M_ROWS * CDIM / 4;
    int n4q = CDIM * 3 * CDIM / 4;
    int n4p = CDIM * CDIM / 4;
    cvt_tf32_kernel<<<(n4h + 255) / 256, 256>>>((const float4*)hidden, (float4*)p_hid_tf, n4h);
    cvt_tf32_kernel<<<(n4q + 255) / 256, 256>>>((const float4*)w_qkv, (float4*)p_wqkv_tf, n4q);
    cvt_tf32_kernel<<<(n4p + 255) / 256, 256>>>((const float4*)w_proj, (float4*)p_wproj_tf, n4p);

    // 1) QKV GEMM + bias + scatter
    dim3 gq(3 * CDIM / GBN, M_ROWS / GBM);   // (18, 196)
    tf32_gemm<<<gq, 256, GEMM_SMEM_B>>>(p_hid_tf, p_wqkv_tf, b_qkv, nullptr, 3 * CDIM, 0);

    // 2) Tensor-core fused attention (writes g_att as tf32 bits)
    attn_tc<<<HEADS, 512, A_SMEM_W * (int)sizeof(float)>>>(rph, rpw);

    // 3) Output projection + bias
    float* p_att;
    cudaGetSymbolAddress((void**)&p_att, g_att);
    dim3 gp(CDIM / GBN, M_ROWS / GBM);       // (6, 196)
    tf32_gemm<<<gp, 256, GEMM_SMEM_B>>>(p_att, p_wproj_tf, b_proj, out, CDIM, 1);
}

// round 6
// speedup vs baseline: 3.4366x; 1.0537x over previous
#include <cuda_runtime.h>
#include <math.h>

// Problem constants
#define HW     196
#define CDIM   768
#define BATCH  128
#define NHEAD  12
#define HEADS  (BATCH * NHEAD)   // 1536
#define HD     64
#define M_ROWS (BATCH * HW)      // 25088

// Scratch
__device__ float g_qkv[(size_t)3 * HEADS * HW * HD];   // [s][head][t][d]
__device__ float g_att[(size_t)M_ROWS * CDIM];         // attn out (tf32 bits)
__device__ float g_hid_tf[(size_t)M_ROWS * CDIM];      // hidden, tf32 bits
__device__ float g_wqkv_tf[(size_t)3 * CDIM * CDIM];   // w_qkv TRANSPOSED [3C][C], tf32
__device__ float g_wproj_tf[(size_t)CDIM * CDIM];      // w_proj TRANSPOSED [C][C], tf32

__device__ __forceinline__ unsigned f2tf(float x) {
    unsigned r;
    asm("cvt.rna.tf32.f32 %0, %1;" : "=r"(r) : "f"(x));
    return r;
}

__device__ __forceinline__ void mma_tf32(float c[4], const unsigned a[4], const unsigned* b) {
    asm volatile(
        "mma.sync.aligned.m16n8k8.row.col.f32.tf32.tf32.f32 "
        "{%0,%1,%2,%3},{%4,%5,%6,%7},{%8,%9},{%0,%1,%2,%3};\n"
        : "+f"(c[0]), "+f"(c[1]), "+f"(c[2]), "+f"(c[3])
        : "r"(a[0]), "r"(a[1]), "r"(a[2]), "r"(a[3]), "r"(b[0]), "r"(b[1]));
}

__device__ __forceinline__ void ldsm4(unsigned r[4], unsigned addr) {
    asm volatile("ldmatrix.sync.aligned.m8n8.x4.shared.b16 {%0,%1,%2,%3}, [%4];"
        : "=r"(r[0]), "=r"(r[1]), "=r"(r[2]), "=r"(r[3]) : "r"(addr));
}

__device__ __forceinline__ void cpa16(float* dst, const float* src) {
    unsigned d = (unsigned)__cvta_generic_to_shared(dst);
    asm volatile("cp.async.cg.shared.global [%0], [%1], 16;\n" :: "r"(d), "l"(src));
}
__device__ __forceinline__ void cpa_commit() {
    asm volatile("cp.async.commit_group;\n");
}
template<int N> __device__ __forceinline__ void cpa_wait() {
    asm volatile("cp.async.wait_group %0;\n" :: "n"(N));
}

// ---------------------------------------------------------------------------
// fp32 -> tf32-bits conversion (plain + transposing variants)
// ---------------------------------------------------------------------------
__global__ __launch_bounds__(256) void cvt_tf32_kernel(
    const float4* __restrict__ in, float4* __restrict__ out, int n4)
{
    int i = blockIdx.x * 256 + threadIdx.x;
    if (i < n4) {
        float4 v = in[i];
        v.x = __uint_as_float(f2tf(v.x));
        v.y = __uint_as_float(f2tf(v.y));
        v.z = __uint_as_float(f2tf(v.z));
        v.w = __uint_as_float(f2tf(v.w));
        out[i] = v;
    }
}

// in: [R][C] row-major -> out: [C][R] row-major, tf32 bits
__global__ __launch_bounds__(256) void cvt_tf32_T(
    const float* __restrict__ in, float* __restrict__ out, int R, int C)
{
    __shared__ float tile[32][33];
    int bx = blockIdx.x * 32, by = blockIdx.y * 32;
    int tx = threadIdx.x & 31, ty = threadIdx.x >> 5;  // 32 x 8
    #pragma unroll
    for (int i = ty; i < 32; i += 8)
        tile[i][tx] = in[(size_t)(by + i) * C + bx + tx];
    __syncthreads();
    #pragma unroll
    for (int i = ty; i < 32; i += 8)
        out[(size_t)(bx + i) * R + by + tx] = __uint_as_float(f2tf(tile[tx][i]));
}

// ---------------------------------------------------------------------------
// tf32 GEMM, ldmatrix fragments, cp.async 3-stage. B is TRANSPOSED [N][K].
// ---------------------------------------------------------------------------
constexpr int GBM = 128, GBN = 128, GBK = 16;
constexpr int TSTR = 20;              // row stride (16 + 4 pad), conflict-free
constexpr int TTILE = 128 * TSTR;     // 2560 words (A and B tiles identical)
constexpr int GEMM_SMEM_B = 6 * TTILE * 4;  // 61440 B

__global__ __launch_bounds__(256, 2) void tf32_gemm(
    const float* __restrict__ A, const float* __restrict__ BT,
    const float* __restrict__ bias, float* __restrict__ Cout,
    int N, int mode)
{
    extern __shared__ float gsm[];
    float* sA = gsm;                   // [3][TTILE]
    float* sB = gsm + 3 * TTILE;       // [3][TTILE]
    unsigned sAb = (unsigned)__cvta_generic_to_shared(sA);
    unsigned sBb = (unsigned)__cvta_generic_to_shared(sB);
    const int K = CDIM;

    int tid = threadIdx.x;
    int warp = tid >> 5, lane = tid & 31;
    int g = lane >> 2, t = lane & 3;
    int wm = warp >> 1, wn = warp & 1;
    int rowbase = wm * 32, colbase = wn * 64;

    const float* Ablk = A + (size_t)blockIdx.y * GBM * K;
    const float* Bblk = BT + (size_t)blockIdx.x * GBN * K;

    float acc[2][8][4];
    #pragma unroll
    for (int mt = 0; mt < 2; mt++)
        #pragma unroll
        for (int nt = 0; nt < 8; nt++)
            #pragma unroll
            for (int r = 0; r < 4; r++) acc[mt][nt][r] = 0.f;

    int cRow[2], cKq[2];
    #pragma unroll
    for (int u = 0; u < 2; u++) {
        int idx = tid + u * 256;
        cRow[u] = idx >> 2; cKq[u] = idx & 3;   // 128 rows x 4 chunks
    }

    #define LOAD_STAGE(k0, s)                                                     \
        do {                                                                      \
            _Pragma("unroll")                                                     \
            for (int u = 0; u < 2; u++) {                                         \
                cpa16(sA + (s) * TTILE + cRow[u] * TSTR + cKq[u] * 4,             \
                      Ablk + (size_t)cRow[u] * K + (k0) + cKq[u] * 4);            \
                cpa16(sB + (s) * TTILE + cRow[u] * TSTR + cKq[u] * 4,             \
                      Bblk + (size_t)cRow[u] * K + (k0) + cKq[u] * 4);            \
            }                                                                     \
        } while (0)

    // ldmatrix per-lane byte offsets within a stage
    unsigned aoff = ((rowbase + (lane & 15)) * TSTR + ((lane >> 4) << 2)) * 4;
    unsigned boff = ((colbase + (lane & 7) + ((lane >= 16) ? 8 : 0)) * TSTR
                     + (((lane >> 3) & 1) << 2)) * 4;

    LOAD_STAGE(0, 0); cpa_commit();
    LOAD_STAGE(GBK, 1); cpa_commit();
    cpa_wait<1>();
    __syncthreads();

    const int NT = K / GBK;  // 48
    for (int it = 0; it < NT; it++) {
        int buf = it % 3;
        if (it + 2 < NT) LOAD_STAGE((it + 2) * GBK, (it + 2) % 3);
        cpa_commit();

        unsigned aS = sAb + buf * TTILE * 4 + aoff;
        unsigned bS = sBb + buf * TTILE * 4 + boff;
        #pragma unroll
        for (int kk = 0; kk < 2; kk++) {
            unsigned afr[2][4], bfr[16];
            #pragma unroll
            for (int mt = 0; mt < 2; mt++)
                ldsm4(afr[mt], aS + mt * 16 * TSTR * 4 + kk * 32);
            #pragma unroll
            for (int np = 0; np < 4; np++)
                ldsm4(&bfr[np * 4], bS + np * 16 * TSTR * 4 + kk * 32);
            #pragma unroll
            for (int mt = 0; mt < 2; mt++)
                #pragma unroll
                for (int nt = 0; nt < 8; nt++)
                    mma_tf32(acc[mt][nt], afr[mt], &bfr[nt * 2]);
        }

        cpa_wait<1>();
        __syncthreads();
    }

    int mrow0 = blockIdx.y * GBM + rowbase;
    int ncol0 = blockIdx.x * GBN + colbase;

    if (mode == 1) {
        #pragma unroll
        for (int mt = 0; mt < 2; mt++)
            #pragma unroll
            for (int nt = 0; nt < 8; nt++)
                #pragma unroll
                for (int rh = 0; rh < 2; rh++)
                    #pragma unroll
                    for (int cl = 0; cl < 2; cl++) {
                        int row = mrow0 + mt * 16 + g + rh * 8;
                        int col = ncol0 + nt * 8 + 2 * t + cl;
                        Cout[(size_t)row * N + col] = acc[mt][nt][rh * 2 + cl] + bias[col];
                    }
    } else {
        #pragma unroll
        for (int mt = 0; mt < 2; mt++)
            #pragma unroll
            for (int rh = 0; rh < 2; rh++) {
                int m = mrow0 + mt * 16 + g + rh * 8;
                int bb = m / HW, tt = m - bb * HW;
                #pragma unroll
                for (int nt = 0; nt < 8; nt++)
                    #pragma unroll
                    for (int cl = 0; cl < 2; cl++) {
                        int n = ncol0 + nt * 8 + 2 * t + cl;
                        int s = n / CDIM;
                        int rem = n - s * CDIM;
                        int h = rem >> 6, d = rem & 63;
                        g_qkv[(((size_t)s * HEADS + bb * NHEAD + h) * HW + tt) * HD + d]
                            = acc[mt][nt][rh * 2 + cl] + bias[n];
                    }
            }
    }
}

// ---------------------------------------------------------------------------
// Tensor-core attention, 512 threads, 1 CTA per head. ldmatrix for K and P
// fragments. S stride 204 (conflict-free ldmatrix rows).
// ---------------------------------------------------------------------------
constexpr int SSTR   = 204;
constexpr int AK_OFF = 0;                    // K tf32: 200 x 68
constexpr int AV_OFF = AK_OFF + 200 * 68;    // V tf32: 200 x 72
constexpr int AS_OFF = AV_OFF + 200 * 72;    // S/P: 112 x 204 (G stage: 208 x 58)
constexpr int AR_OFF = AS_OFF + 112 * SSTR;  // rel: 5488 (Tab stage 56x68 first)
constexpr int A_SMEM_W = AR_OFF + 5488;      // 56336 words = 225344 B
constexpr int GSTR = 58;

__global__ __launch_bounds__(512) void attn_tc(
    const float* __restrict__ rel_h_tab, const float* __restrict__ rel_w_tab)
{
    extern __shared__ float sm[];
    unsigned* smu = (unsigned*)sm;
    unsigned sbase = (unsigned)__cvta_generic_to_shared(sm);
    float* sK  = sm + AK_OFF;   unsigned* sKu = smu + AK_OFF;
    float* sV  = sm + AV_OFF;   unsigned* sVu = smu + AV_OFF;
    float* sS  = sm + AS_OFF;   unsigned* sSu = smu + AS_OFF;
    float* rel = sm + AR_OFF;   unsigned* sTb = smu + AR_OFF;

    int head = blockIdx.x;
    int tid  = threadIdx.x;
    int warp = tid >> 5, lane = tid & 31;
    int g = lane >> 2, t = lane & 3;

    const float* qg = g_qkv + (size_t)head * HW * HD;
    const float* kg = qg + (size_t)HEADS * HW * HD;
    const float* vg = kg + (size_t)HEADS * HW * HD;

    // ---- loads ----
    for (int idx = tid; idx < HW * 16; idx += 512) {
        int r = idx >> 4, c4 = (idx & 15) << 2;
        float4 k = *(const float4*)(kg + r * 64 + c4);
        float4 v = *(const float4*)(vg + r * 64 + c4);
        unsigned* ks = sKu + r * 68 + c4;
        ks[0] = f2tf(k.x); ks[1] = f2tf(k.y); ks[2] = f2tf(k.z); ks[3] = f2tf(k.w);
        unsigned* vs = sVu + r * 72 + c4;
        vs[0] = f2tf(v.x); vs[1] = f2tf(v.y); vs[2] = f2tf(v.z); vs[3] = f2tf(v.w);
    }
    for (int idx = tid; idx < 4 * 72; idx += 512) sV[196 * 72 + idx] = 0.f;
    for (int idx = tid; idx < 4 * 68; idx += 512) sK[196 * 68 + idx] = 0.f;
    for (int idx = tid; idx < 56 * 64; idx += 512) {
        int j = idx >> 6, d = idx & 63;
        float v = (j < 27) ? rel_h_tab[j * 64 + d]
                 : (j < 54) ? rel_w_tab[(j - 27) * 64 + d] : 0.f;
        sTb[j * 68 + d] = f2tf(v);
    }
    __syncthreads();

    // ---- G = Q @ Tab^T (warps 0..12) ----
    if (warp < 13) {
        int r0 = warp * 16;
        unsigned qf[8][4];
        #pragma unroll
        for (int ks = 0; ks < 8; ks++) {
            qf[ks][0] = f2tf(qg[(r0 + g) * 64 + ks * 8 + t]);
            qf[ks][1] = f2tf(qg[(r0 + g + 8) * 64 + ks * 8 + t]);
            qf[ks][2] = f2tf(qg[(r0 + g) * 64 + ks * 8 + t + 4]);
            qf[ks][3] = f2tf(qg[(r0 + g + 8) * 64 + ks * 8 + t + 4]);
        }
        unsigned tb = sbase + (AR_OFF + (lane & 7) * 68 + (lane >> 3) * 4) * 4;
        #pragma unroll
        for (int n0 = 0; n0 < 7; n0++) {
            unsigned tfr[16];
            #pragma unroll
            for (int j = 0; j < 4; j++)
                ldsm4(&tfr[4 * j], tb + (n0 * 8 * 68 + j * 16) * 4);
            float c4[4] = {0.f, 0.f, 0.f, 0.f};
            #pragma unroll
            for (int ks = 0; ks < 8; ks++)
                mma_tf32(c4, qf[ks], &tfr[2 * ks]);
            *(float2*)&sS[(r0 + g) * GSTR + n0 * 8 + 2 * t]     = make_float2(c4[0], c4[1]);
            *(float2*)&sS[(r0 + g + 8) * GSTR + n0 * 8 + 2 * t] = make_float2(c4[2], c4[3]);
        }
    }
    __syncthreads();

    // ---- gather G -> rel ----
    for (int idx = tid; idx < 5488; idx += 512) {
        int row = idx / 28, c = idx - row * 28;
        if (c < 14)
            rel[row * 14 + c] = sS[row * GSTR + (row / 14 - c + 13)];
        else
            rel[2744 + row * 14 + (c - 14)] = sS[row * GSTR + 27 + (row % 14) - (c - 14) + 13];
    }
    __syncthreads();

    int bb = head / NHEAD, hh = head - bb * NHEAD;
    float* outp = g_att + (size_t)bb * HW * CDIM + hh * HD;
    const float scale = 0.125f;

    #pragma unroll
    for (int blk = 0; blk < 2; blk++) {
        int ntiles = (blk == 0) ? 7 : 6;
        bool act = (warp >> 1) < ntiles;
        int mt  = blk * 7 + (warp >> 1);
        int lr0 = (warp >> 1) * 16;
        int half = warp & 1;

        unsigned qf[8][4];
        if (act) {
            int r0 = mt * 16;
            #pragma unroll
            for (int ks = 0; ks < 8; ks++) {
                qf[ks][0] = f2tf(qg[(r0 + g) * 64 + ks * 8 + t]);
                qf[ks][1] = f2tf(qg[(r0 + g + 8) * 64 + ks * 8 + t]);
                qf[ks][2] = f2tf(qg[(r0 + g) * 64 + ks * 8 + t + 4]);
                qf[ks][3] = f2tf(qg[(r0 + g + 8) * 64 + ks * 8 + t + 4]);
            }
        }

        // ---- S = Q K^T (ldmatrix K frags) ----
        if (act) {
            unsigned kb = sbase + ((lane & 7) * 68 + (lane >> 3) * 4) * 4;
            int n0beg = half * 13, n0end = n0beg + 13 - half;
            for (int n0 = n0beg; n0 < n0end; n0++) {
                unsigned kfr[16];
                #pragma unroll
                for (int j = 0; j < 4; j++)
                    ldsm4(&kfr[4 * j], kb + (n0 * 8 * 68 + j * 16) * 4);
                float c4[4] = {0.f, 0.f, 0.f, 0.f};
                #pragma unroll
                for (int ks = 0; ks < 8; ks++)
                    mma_tf32(c4, qf[ks], &kfr[2 * ks]);
                *(float2*)&sS[(lr0 + g) * SSTR + n0 * 8 + 2 * t]     = make_float2(c4[0], c4[1]);
                *(float2*)&sS[(lr0 + g + 8) * SSTR + n0 * 8 + 2 * t] = make_float2(c4[2], c4[3]);
            }
        }
        __syncthreads();

        // ---- softmax rows ----
        int nrows = (blk == 0) ? 112 : 84;
        int growb = blk * 112;
        for (int lr = warp; lr < nrows; lr += 16) {
            int grow = growb + lr;
            float vals[7];
            float mx = -1e30f;
            #pragma unroll
            for (int i = 0; i < 7; i++) {
                int j = lane + 32 * i;
                float v;
                if (j < HW)
                    v = fmaf(sS[lr * SSTR + j], scale,
                             rel[grow * 14 + j / 14] + rel[2744 + grow * 14 + j % 14]);
                else v = -1e30f;
                vals[i] = v;
                mx = fmaxf(mx, v);
            }
            #pragma unroll
            for (int off = 16; off; off >>= 1)
                mx = fmaxf(mx, __shfl_xor_sync(0xffffffffu, mx, off));
            float sum = 0.f;
            #pragma unroll
            for (int i = 0; i < 7; i++) {
                int j = lane + 32 * i;
                float e = (j < HW) ? __expf(vals[i] - mx) : 0.f;
                vals[i] = e;
                sum += e;
            }
            #pragma unroll
            for (int off = 16; off; off >>= 1)
                sum += __shfl_xor_sync(0xffffffffu, sum, off);
            float inv = 1.f / sum;
            #pragma unroll
            for (int i = 0; i < 7; i++) {
                int j = lane + 32 * i;
                if (j < HW)       sSu[lr * SSTR + j] = f2tf(vals[i] * inv);
                else if (j < SSTR) sSu[lr * SSTR + j] = 0u;
            }
        }
        __syncthreads();

        // ---- O = P V (ldmatrix P frags) ----
        if (act) {
            int ntb = half * 4;
            float oacc[4][4];
            #pragma unroll
            for (int nt = 0; nt < 4; nt++)
                #pragma unroll
                for (int r = 0; r < 4; r++) oacc[nt][r] = 0.f;

            unsigned pb = sbase + (AS_OFF + (lr0 + (lane & 15)) * SSTR
                                   + ((lane >= 16) ? 4 : 0)) * 4;
            for (int ks = 0; ks < 25; ks++) {
                unsigned a[4];
                ldsm4(a, pb + ks * 32);
                #pragma unroll
                for (int nt = 0; nt < 4; nt++) {
                    unsigned bfr[2];
                    bfr[0] = sVu[(ks * 8 + t) * 72 + (ntb + nt) * 8 + g];
                    bfr[1] = sVu[(ks * 8 + t + 4) * 72 + (ntb + nt) * 8 + g];
                    mma_tf32(oacc[nt], a, bfr);
                }
            }
            #pragma unroll
            for (int rh = 0; rh < 2; rh++) {
                int row = mt * 16 + g + rh * 8;
                if (row < HW) {
                    #pragma unroll
                    for (int nt = 0; nt < 4; nt++) {
                        float2 w;
                        w.x = __uint_as_float(f2tf(oacc[nt][rh * 2]));
                        w.y = __uint_as_float(f2tf(oacc[nt][rh * 2 + 1]));
                        *(float2*)&outp[(size_t)row * CDIM + (ntb + nt) * 8 + 2 * t] = w;
                    }
                }
            }
        }
        __syncthreads();
    }
}

// ---------------------------------------------------------------------------
extern "C" void kernel_launch(void* const* d_in, const int* in_sizes, int n_in,
                              void* d_out, int out_size)
{
    const float* hidden = (const float*)d_in[0];
    const float* w_qkv  = (const float*)d_in[1];
    const float* b_qkv  = (const float*)d_in[2];
    const float* rph    = (const float*)d_in[3];
    const float* rpw    = (const float*)d_in[4];
    const float* w_proj = (const float*)d_in[5];
    const float* b_proj = (const float*)d_in[6];
    float* out = (float*)d_out;

    (void)in_sizes; (void)n_in; (void)out_size;

    cudaFuncSetAttribute(attn_tc, cudaFuncAttributeMaxDynamicSharedMemorySize,
                         A_SMEM_W * (int)sizeof(float));
    cudaFuncSetAttribute(tf32_gemm, cudaFuncAttributeMaxDynamicSharedMemorySize,
                         GEMM_SMEM_B);

    float *p_hid_tf, *p_wqkv_tf, *p_wproj_tf, *p_att;
    cudaGetSymbolAddress((void**)&p_hid_tf,   g_hid_tf);
    cudaGetSymbolAddress((void**)&p_wqkv_tf,  g_wqkv_tf);
    cudaGetSymbolAddress((void**)&p_wproj_tf, g_wproj_tf);
    cudaGetSymbolAddress((void**)&p_att,      g_att);

    // 0) pre-convert: hidden (plain), weights (transposed to [N][K])
    int n4h = M_ROWS * CDIM / 4;
    cvt_tf32_kernel<<<(n4h + 255) / 256, 256>>>((const float4*)hidden, (float4*)p_hid_tf, n4h);
    cvt_tf32_T<<<dim3(3 * CDIM / 32, CDIM / 32), 256>>>(w_qkv, p_wqkv_tf, CDIM, 3 * CDIM);
    cvt_tf32_T<<<dim3(CDIM / 32, CDIM / 32), 256>>>(w_proj, p_wproj_tf, CDIM, CDIM);

    // 1) QKV GEMM + bias + scatter
    dim3 gq(3 * CDIM / GBN, M_ROWS / GBM);   // (18, 196)
    tf32_gemm<<<gq, 256, GEMM_SMEM_B>>>(p_hid_tf, p_wqkv_tf, b_qkv, nullptr, 3 * CDIM, 0);

    // 2) Tensor-core fused attention (writes g_att as tf32 bits)
    attn_tc<<<HEADS, 512, A_SMEM_W * (int)sizeof(float)>>>(rph, rpw);

    // 3) Output projection + bias
    dim3 gp(CDIM / GBN, M_ROWS / GBM);       // (6, 196)
    tf32_gemm<<<gp, 256, GEMM_SMEM_B>>>(p_att, p_wproj_tf, b_proj, out, CDIM, 1);
}

// round 8
// speedup vs baseline: 3.5032x; 1.0194x over previous
#include <cuda_runtime.h>
#include <math.h>

// Problem constants
#define HW     196
#define CDIM   768
#define BATCH  128
#define NHEAD  12
#define HEADS  (BATCH * NHEAD)   // 1536
#define HD     64
#define M_ROWS (BATCH * HW)      // 25088

// Scratch
__device__ float g_qkv[(size_t)3 * HEADS * HW * HD];   // [s][head][t][d]
__device__ float g_att[(size_t)M_ROWS * CDIM];         // attn out (tf32 bits)
__device__ float g_hid_tf[(size_t)M_ROWS * CDIM];      // hidden, tf32 bits
__device__ float g_wqkv_tf[(size_t)3 * CDIM * CDIM];   // w_qkv TRANSPOSED [3C][C], tf32
__device__ float g_wproj_tf[(size_t)CDIM * CDIM];      // w_proj TRANSPOSED [C][C], tf32

__device__ __forceinline__ unsigned f2tf(float x) {
    unsigned r;
    asm("cvt.rna.tf32.f32 %0, %1;" : "=r"(r) : "f"(x));
    return r;
}

__device__ __forceinline__ void mma_tf32(float c[4], const unsigned a[4], const unsigned* b) {
    asm volatile(
        "mma.sync.aligned.m16n8k8.row.col.f32.tf32.tf32.f32 "
        "{%0,%1,%2,%3},{%4,%5,%6,%7},{%8,%9},{%0,%1,%2,%3};\n"
        : "+f"(c[0]), "+f"(c[1]), "+f"(c[2]), "+f"(c[3])
        : "r"(a[0]), "r"(a[1]), "r"(a[2]), "r"(a[3]), "r"(b[0]), "r"(b[1]));
}

__device__ __forceinline__ void ldsm4(unsigned r[4], unsigned addr) {
    asm volatile("ldmatrix.sync.aligned.m8n8.x4.shared.b16 {%0,%1,%2,%3}, [%4];"
        : "=r"(r[0]), "=r"(r[1]), "=r"(r[2]), "=r"(r[3]) : "r"(addr));
}

__device__ __forceinline__ void cpa16(float* dst, const float* src) {
    unsigned d = (unsigned)__cvta_generic_to_shared(dst);
    asm volatile("cp.async.cg.shared.global [%0], [%1], 16;\n" :: "r"(d), "l"(src));
}
__device__ __forceinline__ void cpa_commit() {
    asm volatile("cp.async.commit_group;\n");
}
template<int N> __device__ __forceinline__ void cpa_wait() {
    asm volatile("cp.async.wait_group %0;\n" :: "n"(N));
}

// ---------------------------------------------------------------------------
// fp32 -> tf32-bits conversion (plain + transposing variants)
// ---------------------------------------------------------------------------
__global__ __launch_bounds__(256) void cvt_tf32_kernel(
    const float4* __restrict__ in, float4* __restrict__ out, int n4)
{
    int i = blockIdx.x * 256 + threadIdx.x;
    if (i < n4) {
        float4 v = in[i];
        v.x = __uint_as_float(f2tf(v.x));
        v.y = __uint_as_float(f2tf(v.y));
        v.z = __uint_as_float(f2tf(v.z));
        v.w = __uint_as_float(f2tf(v.w));
        out[i] = v;
    }
}

// in: [R][C] row-major -> out: [C][R] row-major, tf32 bits
__global__ __launch_bounds__(256) void cvt_tf32_T(
    const float* __restrict__ in, float* __restrict__ out, int R, int C)
{
    __shared__ float tile[32][33];
    int bx = blockIdx.x * 32, by = blockIdx.y * 32;
    int tx = threadIdx.x & 31, ty = threadIdx.x >> 5;  // 32 x 8
    #pragma unroll
    for (int i = ty; i < 32; i += 8)
        tile[i][tx] = in[(size_t)(by + i) * C + bx + tx];
    __syncthreads();
    #pragma unroll
    for (int i = ty; i < 32; i += 8)
        out[(size_t)(bx + i) * R + by + tx] = __uint_as_float(f2tf(tile[tx][i]));
}

// ---------------------------------------------------------------------------
// tf32 GEMM, ldmatrix + register-double-buffered fragments, cp.async 3-stage.
// B is TRANSPOSED [N][K]. Mid-iteration barrier fences the cross-iteration
// fragment prefetch (fixes round-7 visibility race).
// ---------------------------------------------------------------------------
constexpr int GBM = 128, GBN = 128, GBK = 16;
constexpr int TSTR = 20;              // row stride (16 + 4 pad), conflict-free
constexpr int TTILE = 128 * TSTR;     // 2560 words
constexpr int GEMM_SMEM_B = 6 * TTILE * 4;  // 61440 B

__global__ __launch_bounds__(256, 2) void tf32_gemm(
    const float* __restrict__ A, const float* __restrict__ BT,
    const float* __restrict__ bias, float* __restrict__ Cout,
    int N, int mode)
{
    extern __shared__ float gsm[];
    float* sA = gsm;                   // [3][TTILE]
    float* sB = gsm + 3 * TTILE;       // [3][TTILE]
    unsigned sAb = (unsigned)__cvta_generic_to_shared(sA);
    unsigned sBb = (unsigned)__cvta_generic_to_shared(sB);
    const int K = CDIM;

    int tid = threadIdx.x;
    int warp = tid >> 5, lane = tid & 31;
    int g = lane >> 2, t = lane & 3;
    int wm = warp >> 1, wn = warp & 1;
    int rowbase = wm * 32, colbase = wn * 64;

    const float* Ablk = A + (size_t)blockIdx.y * GBM * K;
    const float* Bblk = BT + (size_t)blockIdx.x * GBN * K;

    float acc[2][8][4];
    #pragma unroll
    for (int mt = 0; mt < 2; mt++)
        #pragma unroll
        for (int nt = 0; nt < 8; nt++)
            #pragma unroll
            for (int r = 0; r < 4; r++) acc[mt][nt][r] = 0.f;

    int cRow[2], cKq[2];
    #pragma unroll
    for (int u = 0; u < 2; u++) {
        int idx = tid + u * 256;
        cRow[u] = idx >> 2; cKq[u] = idx & 3;
    }

    #define LOAD_STAGE(k0, s)                                                     \
        do {                                                                      \
            _Pragma("unroll")                                                     \
            for (int u = 0; u < 2; u++) {                                         \
                cpa16(sA + (s) * TTILE + cRow[u] * TSTR + cKq[u] * 4,             \
                      Ablk + (size_t)cRow[u] * K + (k0) + cKq[u] * 4);            \
                cpa16(sB + (s) * TTILE + cRow[u] * TSTR + cKq[u] * 4,             \
                      Bblk + (size_t)cRow[u] * K + (k0) + cKq[u] * 4);            \
            }                                                                     \
        } while (0)

    // ldmatrix per-lane byte offsets within a stage
    unsigned aoff = ((rowbase + (lane & 15)) * TSTR + ((lane >> 4) << 2)) * 4;
    unsigned boff = ((colbase + (lane & 7) + ((lane >= 16) ? 8 : 0)) * TSTR
                     + (((lane >> 3) & 1) << 2)) * 4;

    // frag register double-buffers
    unsigned afr[2][2][4];
    unsigned bfr[2][16];

    #define LDFRAGS(pp, aS, bS, kk)                                               \
        do {                                                                      \
            _Pragma("unroll")                                                     \
            for (int mt = 0; mt < 2; mt++)                                        \
                ldsm4(afr[pp][mt], (aS) + mt * 16 * TSTR * 4 + (kk) * 32);        \
            _Pragma("unroll")                                                     \
            for (int np = 0; np < 4; np++)                                        \
                ldsm4(&bfr[pp][np * 4], (bS) + np * 16 * TSTR * 4 + (kk) * 32);   \
        } while (0)

    #define DOMMA(pp)                                                             \
        do {                                                                      \
            _Pragma("unroll")                                                     \
            for (int mt = 0; mt < 2; mt++)                                        \
                _Pragma("unroll")                                                 \
                for (int nt = 0; nt < 8; nt++)                                    \
                    mma_tf32(acc[mt][nt], afr[pp][mt], &bfr[pp][nt * 2]);         \
        } while (0)

    LOAD_STAGE(0, 0); cpa_commit();
    LOAD_STAGE(GBK, 1); cpa_commit();
    cpa_wait<1>();
    __syncthreads();
    LDFRAGS(0, sAb + aoff, sBb + boff, 0);   // stage 0, kk=0 (fenced above)

    const int NT = K / GBK;  // 48
    for (int it = 0; it < NT; it++) {
        int buf = it % 3, nbuf = (it + 1) % 3;
        // prefetch stage it+2 (overwrites stage (it-1)%3: its last reads were
        // before iteration it-1's mid-barrier -> ordered)
        if (it + 2 < NT) LOAD_STAGE((it + 2) * GBK, (it + 2) % 3);
        cpa_commit();

        unsigned aC = sAb + buf * TTILE * 4 + aoff;
        unsigned bC = sBb + buf * TTILE * 4 + boff;
        LDFRAGS(1, aC, bC, 1);        // kk=1 frags in flight (stage fenced)
        DOMMA(0);                      // MMAs on kk=0

        if (it + 1 < NT) {
            cpa_wait<1>();             // stage it+1 complete (this thread)
            __syncthreads();           // ... and visible from ALL threads
            unsigned aN = sAb + nbuf * TTILE * 4 + aoff;
            unsigned bN = sBb + nbuf * TTILE * 4 + boff;
            LDFRAGS(0, aN, bN, 0);    // next-iter kk=0 frags in flight
        }
        DOMMA(1);                      // MMAs on kk=1
    }

    int mrow0 = blockIdx.y * GBM + rowbase;
    int ncol0 = blockIdx.x * GBN + colbase;

    if (mode == 1) {
        #pragma unroll
        for (int mt = 0; mt < 2; mt++)
            #pragma unroll
            for (int nt = 0; nt < 8; nt++)
                #pragma unroll
                for (int rh = 0; rh < 2; rh++)
                    #pragma unroll
                    for (int cl = 0; cl < 2; cl++) {
                        int row = mrow0 + mt * 16 + g + rh * 8;
                        int col = ncol0 + nt * 8 + 2 * t + cl;
                        Cout[(size_t)row * N + col] = acc[mt][nt][rh * 2 + cl] + bias[col];
                    }
    } else {
        #pragma unroll
        for (int mt = 0; mt < 2; mt++)
            #pragma unroll
            for (int rh = 0; rh < 2; rh++) {
                int m = mrow0 + mt * 16 + g + rh * 8;
                int bb = m / HW, tt = m - bb * HW;
                #pragma unroll
                for (int nt = 0; nt < 8; nt++)
                    #pragma unroll
                    for (int cl = 0; cl < 2; cl++) {
                        int n = ncol0 + nt * 8 + 2 * t + cl;
                        int s = n / CDIM;
                        int rem = n - s * CDIM;
                        int h = rem >> 6, d = rem & 63;
                        g_qkv[(((size_t)s * HEADS + bb * NHEAD + h) * HW + tt) * HD + d]
                            = acc[mt][nt][rh * 2 + cl] + bias[n];
                    }
            }
    }
}

// ---------------------------------------------------------------------------
// Tensor-core attention, 512 threads, 1 CTA per head. Split accumulator
// chains; register-pipelined P frags in PV.
// ---------------------------------------------------------------------------
constexpr int SSTR   = 204;
constexpr int AK_OFF = 0;                    // K tf32: 200 x 68
constexpr int AV_OFF = AK_OFF + 200 * 68;    // V tf32: 200 x 72
constexpr int AS_OFF = AV_OFF + 200 * 72;    // S/P: 112 x 204 (G stage: 208 x 58)
constexpr int AR_OFF = AS_OFF + 112 * SSTR;  // rel: 5488 (Tab stage 56x68 first)
constexpr int A_SMEM_W = AR_OFF + 5488;      // 56336 words = 225344 B
constexpr int GSTR = 58;

__global__ __launch_bounds__(512) void attn_tc(
    const float* __restrict__ rel_h_tab, const float* __restrict__ rel_w_tab)
{
    extern __shared__ float sm[];
    unsigned* smu = (unsigned*)sm;
    unsigned sbase = (unsigned)__cvta_generic_to_shared(sm);
    float* sK  = sm + AK_OFF;   unsigned* sKu = smu + AK_OFF;
    float* sV  = sm + AV_OFF;   unsigned* sVu = smu + AV_OFF;
    float* sS  = sm + AS_OFF;   unsigned* sSu = smu + AS_OFF;
    float* rel = sm + AR_OFF;   unsigned* sTb = smu + AR_OFF;

    int head = blockIdx.x;
    int tid  = threadIdx.x;
    int warp = tid >> 5, lane = tid & 31;
    int g = lane >> 2, t = lane & 3;

    const float* qg = g_qkv + (size_t)head * HW * HD;
    const float* kg = qg + (size_t)HEADS * HW * HD;
    const float* vg = kg + (size_t)HEADS * HW * HD;

    // ---- loads ----
    for (int idx = tid; idx < HW * 16; idx += 512) {
        int r = idx >> 4, c4 = (idx & 15) << 2;
        float4 k = *(const float4*)(kg + r * 64 + c4);
        float4 v = *(const float4*)(vg + r * 64 + c4);
        unsigned* ks = sKu + r * 68 + c4;
        ks[0] = f2tf(k.x); ks[1] = f2tf(k.y); ks[2] = f2tf(k.z); ks[3] = f2tf(k.w);
        unsigned* vs = sVu + r * 72 + c4;
        vs[0] = f2tf(v.x); vs[1] = f2tf(v.y); vs[2] = f2tf(v.z); vs[3] = f2tf(v.w);
    }
    for (int idx = tid; idx < 4 * 72; idx += 512) sV[196 * 72 + idx] = 0.f;
    for (int idx = tid; idx < 4 * 68; idx += 512) sK[196 * 68 + idx] = 0.f;
    for (int idx = tid; idx < 56 * 64; idx += 512) {
        int j = idx >> 6, d = idx & 63;
        float v = (j < 27) ? rel_h_tab[j * 64 + d]
                 : (j < 54) ? rel_w_tab[(j - 27) * 64 + d] : 0.f;
        sTb[j * 68 + d] = f2tf(v);
    }
    __syncthreads();

    // ---- G = Q @ Tab^T (warps 0..12) ----
    if (warp < 13) {
        int r0 = warp * 16;
        unsigned qf[8][4];
        #pragma unroll
        for (int ks = 0; ks < 8; ks++) {
            qf[ks][0] = f2tf(qg[(r0 + g) * 64 + ks * 8 + t]);
            qf[ks][1] = f2tf(qg[(r0 + g + 8) * 64 + ks * 8 + t]);
            qf[ks][2] = f2tf(qg[(r0 + g) * 64 + ks * 8 + t + 4]);
            qf[ks][3] = f2tf(qg[(r0 + g + 8) * 64 + ks * 8 + t + 4]);
        }
        unsigned tb = sbase + (AR_OFF + (lane & 7) * 68 + (lane >> 3) * 4) * 4;
        #pragma unroll
        for (int n0 = 0; n0 < 7; n0++) {
            unsigned tfr[16];
            #pragma unroll
            for (int j = 0; j < 4; j++)
                ldsm4(&tfr[4 * j], tb + (n0 * 8 * 68 + j * 16) * 4);
            float c4a[4] = {0.f, 0.f, 0.f, 0.f};
            float c4b[4] = {0.f, 0.f, 0.f, 0.f};
            #pragma unroll
            for (int ks = 0; ks < 4; ks++) mma_tf32(c4a, qf[ks], &tfr[2 * ks]);
            #pragma unroll
            for (int ks = 4; ks < 8; ks++) mma_tf32(c4b, qf[ks], &tfr[2 * ks]);
            #pragma unroll
            for (int r = 0; r < 4; r++) c4a[r] += c4b[r];
            *(float2*)&sS[(r0 + g) * GSTR + n0 * 8 + 2 * t]     = make_float2(c4a[0], c4a[1]);
            *(float2*)&sS[(r0 + g + 8) * GSTR + n0 * 8 + 2 * t] = make_float2(c4a[2], c4a[3]);
        }
    }
    __syncthreads();

    // ---- gather G -> rel ----
    for (int idx = tid; idx < 5488; idx += 512) {
        int row = idx / 28, c = idx - row * 28;
        if (c < 14)
            rel[row * 14 + c] = sS[row * GSTR + (row / 14 - c + 13)];
        else
            rel[2744 + row * 14 + (c - 14)] = sS[row * GSTR + 27 + (row % 14) - (c - 14) + 13];
    }
    __syncthreads();

    int bb = head / NHEAD, hh = head - bb * NHEAD;
    float* outp = g_att + (size_t)bb * HW * CDIM + hh * HD;
    const float scale = 0.125f;

    #pragma unroll
    for (int blk = 0; blk < 2; blk++) {
        int ntiles = (blk == 0) ? 7 : 6;
        bool act = (warp >> 1) < ntiles;
        int mt  = blk * 7 + (warp >> 1);
        int lr0 = (warp >> 1) * 16;
        int half = warp & 1;

        unsigned qf[8][4];
        if (act) {
            int r0 = mt * 16;
            #pragma unroll
            for (int ks = 0; ks < 8; ks++) {
                qf[ks][0] = f2tf(qg[(r0 + g) * 64 + ks * 8 + t]);
                qf[ks][1] = f2tf(qg[(r0 + g + 8) * 64 + ks * 8 + t]);
                qf[ks][2] = f2tf(qg[(r0 + g) * 64 + ks * 8 + t + 4]);
                qf[ks][3] = f2tf(qg[(r0 + g + 8) * 64 + ks * 8 + t + 4]);
            }
        }

        // ---- S = Q K^T (ldmatrix K frags, split acc chains) ----
        if (act) {
            unsigned kb = sbase + ((lane & 7) * 68 + (lane >> 3) * 4) * 4;
            int n0beg = half * 13, n0end = n0beg + 13 - half;
            for (int n0 = n0beg; n0 < n0end; n0++) {
                unsigned kfr[16];
                #pragma unroll
                for (int j = 0; j < 4; j++)
                    ldsm4(&kfr[4 * j], kb + (n0 * 8 * 68 + j * 16) * 4);
                float c4a[4] = {0.f, 0.f, 0.f, 0.f};
                float c4b[4] = {0.f, 0.f, 0.f, 0.f};
                #pragma unroll
                for (int ks = 0; ks < 4; ks++) mma_tf32(c4a, qf[ks], &kfr[2 * ks]);
                #pragma unroll
                for (int ks = 4; ks < 8; ks++) mma_tf32(c4b, qf[ks], &kfr[2 * ks]);
                #pragma unroll
                for (int r = 0; r < 4; r++) c4a[r] += c4b[r];
                *(float2*)&sS[(lr0 + g) * SSTR + n0 * 8 + 2 * t]     = make_float2(c4a[0], c4a[1]);
                *(float2*)&sS[(lr0 + g + 8) * SSTR + n0 * 8 + 2 * t] = make_float2(c4a[2], c4a[3]);
            }
        }
        __syncthreads();

        // ---- softmax rows ----
        int nrows = (blk == 0) ? 112 : 84;
        int growb = blk * 112;
        for (int lr = warp; lr < nrows; lr += 16) {
            int grow = growb + lr;
            float vals[7];
            float mx = -1e30f;
            #pragma unroll
            for (int i = 0; i < 7; i++) {
                int j = lane + 32 * i;
                float v;
                if (j < HW)
                    v = fmaf(sS[lr * SSTR + j], scale,
                             rel[grow * 14 + j / 14] + rel[2744 + grow * 14 + j % 14]);
                else v = -1e30f;
                vals[i] = v;
                mx = fmaxf(mx, v);
            }
            #pragma unroll
            for (int off = 16; off; off >>= 1)
                mx = fmaxf(mx, __shfl_xor_sync(0xffffffffu, mx, off));
            float sum = 0.f;
            #pragma unroll
            for (int i = 0; i < 7; i++) {
                int j = lane + 32 * i;
                float e = (j < HW) ? __expf(vals[i] - mx) : 0.f;
                vals[i] = e;
                sum += e;
            }
            #pragma unroll
            for (int off = 16; off; off >>= 1)
                sum += __shfl_xor_sync(0xffffffffu, sum, off);
            float inv = 1.f / sum;
            #pragma unroll
            for (int i = 0; i < 7; i++) {
                int j = lane + 32 * i;
                if (j < HW)       sSu[lr * SSTR + j] = f2tf(vals[i] * inv);
                else if (j < SSTR) sSu[lr * SSTR + j] = 0u;
            }
        }
        __syncthreads();

        // ---- O = P V (register-pipelined P frags) ----
        if (act) {
            int ntb = half * 4;
            float oacc[4][4];
            #pragma unroll
            for (int nt = 0; nt < 4; nt++)
                #pragma unroll
                for (int r = 0; r < 4; r++) oacc[nt][r] = 0.f;

            unsigned pb = sbase + (AS_OFF + (lr0 + (lane & 15)) * SSTR
                                   + ((lane >= 16) ? 4 : 0)) * 4;
            unsigned aP[2][4];
            ldsm4(aP[0], pb);
            for (int ks = 0; ks < 25; ks++) {
                int cur = ks & 1;
                if (ks < 24) ldsm4(aP[cur ^ 1], pb + (ks + 1) * 32);
                #pragma unroll
                for (int nt = 0; nt < 4; nt++) {
                    unsigned bfr[2];
                    bfr[0] = sVu[(ks * 8 + t) * 72 + (ntb + nt) * 8 + g];
                    bfr[1] = sVu[(ks * 8 + t + 4) * 72 + (ntb + nt) * 8 + g];
                    mma_tf32(oacc[nt], aP[cur], bfr);
                }
            }
            #pragma unroll
            for (int rh = 0; rh < 2; rh++) {
                int row = mt * 16 + g + rh * 8;
                if (row < HW) {
                    #pragma unroll
                    for (int nt = 0; nt < 4; nt++) {
                        float2 w;
                        w.x = __uint_as_float(f2tf(oacc[nt][rh * 2]));
                        w.y = __uint_as_float(f2tf(oacc[nt][rh * 2 + 1]));
                        *(float2*)&outp[(size_t)row * CDIM + (ntb + nt) * 8 + 2 * t] = w;
                    }
                }
            }
        }
        __syncthreads();
    }
}

// ---------------------------------------------------------------------------
extern "C" void kernel_launch(void* const* d_in, const int* in_sizes, int n_in,
                              void* d_out, int out_size)
{
    const float* hidden = (const float*)d_in[0];
    const float* w_qkv  = (const float*)d_in[1];
    const float* b_qkv  = (const float*)d_in[2];
    const float* rph    = (const float*)d_in[3];
    const float* rpw    = (const float*)d_in[4];
    const float* w_proj = (const float*)d_in[5];
    const float* b_proj = (const float*)d_in[6];
    float* out = (float*)d_out;

    (void)in_sizes; (void)n_in; (void)out_size;

    cudaFuncSetAttribute(attn_tc, cudaFuncAttributeMaxDynamicSharedMemorySize,
                         A_SMEM_W * (int)sizeof(float));
    cudaFuncSetAttribute(tf32_gemm, cudaFuncAttributeMaxDynamicSharedMemorySize,
                         GEMM_SMEM_B);

    float *p_hid_tf, *p_wqkv_tf, *p_wproj_tf, *p_att;
    cudaGetSymbolAddress((void**)&p_hid_tf,   g_hid_tf);
    cudaGetSymbolAddress((void**)&p_wqkv_tf,  g_wqkv_tf);
    cudaGetSymbolAddress((void**)&p_wproj_tf, g_wproj_tf);
    cudaGetSymbolAddress((void**)&p_att,      g_att);

    // 0) pre-convert: hidden (plain), weights (transposed to [N][K])
    int n4h = M_ROWS * CDIM / 4;
    cvt_tf32_kernel<<<(n4h + 255) / 256, 256>>>((const float4*)hidden, (float4*)p_hid_tf, n4h);
    cvt_tf32_T<<<dim3(3 * CDIM / 32, CDIM / 32), 256>>>(w_qkv, p_wqkv_tf, CDIM, 3 * CDIM);
    cvt_tf32_T<<<dim3(CDIM / 32, CDIM / 32), 256>>>(w_proj, p_wproj_tf, CDIM, CDIM);

    // 1) QKV GEMM + bias + scatter
    dim3 gq(3 * CDIM / GBN, M_ROWS / GBM);   // (18, 196)
    tf32_gemm<<<gq, 256, GEMM_SMEM_B>>>(p_hid_tf, p_wqkv_tf, b_qkv, nullptr, 3 * CDIM, 0);

    // 2) Tensor-core fused attention (writes g_att as tf32 bits)
    attn_tc<<<HEADS, 512, A_SMEM_W * (int)sizeof(float)>>>(rph, rpw);

    // 3) Output projection + bias
    dim3 gp(CDIM / GBN, M_ROWS / GBM);       // (6, 196)
    tf32_gemm<<<gp, 256, GEMM_SMEM_B>>>(p_att, p_wproj_tf, b_proj, out, CDIM, 1);
}

// round 12
// speedup vs baseline: 3.6241x; 1.0345x over previous
#include <cuda_runtime.h>
#include <cstdint>
#include <math.h>

// Problem constants
#define HW     196
#define CDIM   768
#define BATCH  128
#define NHEAD  12
#define HEADS  (BATCH * NHEAD)   // 1536
#define HD     64
#define M_ROWS (BATCH * HW)      // 25088

// Scratch
__device__ float g_qkv[(size_t)3 * HEADS * HW * HD];   // [s][head][t][d]
__device__ float g_att[(size_t)M_ROWS * CDIM];         // attn out (tf32 bits)
__device__ float g_hid_tf[(size_t)M_ROWS * CDIM];      // hidden, tf32 bits
__device__ float g_wqkv_tf[(size_t)3 * CDIM * CDIM];   // w_qkv TRANSPOSED [3C][C], tf32
__device__ float g_wproj_tf[(size_t)CDIM * CDIM];      // w_proj TRANSPOSED [C][C], tf32

__device__ __forceinline__ unsigned f2tf(float x) {
    unsigned r;
    asm("cvt.rna.tf32.f32 %0, %1;" : "=r"(r) : "f"(x));
    return r;
}

__device__ __forceinline__ void mma_tf32(float c[4], const unsigned a[4], const unsigned* b) {
    asm volatile(
        "mma.sync.aligned.m16n8k8.row.col.f32.tf32.tf32.f32 "
        "{%0,%1,%2,%3},{%4,%5,%6,%7},{%8,%9},{%0,%1,%2,%3};\n"
        : "+f"(c[0]), "+f"(c[1]), "+f"(c[2]), "+f"(c[3])
        : "r"(a[0]), "r"(a[1]), "r"(a[2]), "r"(a[3]), "r"(b[0]), "r"(b[1]));
}

__device__ __forceinline__ void ldsm4(unsigned r[4], unsigned addr) {
    asm volatile("ldmatrix.sync.aligned.m8n8.x4.shared.b16 {%0,%1,%2,%3}, [%4];"
        : "=r"(r[0]), "=r"(r[1]), "=r"(r[2]), "=r"(r[3]) : "r"(addr));
}

__device__ __forceinline__ void cpa16s(uint32_t dst, const float* src) {
    asm volatile("cp.async.cg.shared.global [%0], [%1], 16;\n" :: "r"(dst), "l"(src));
}
__device__ __forceinline__ void cpa_commit() {
    asm volatile("cp.async.commit_group;\n");
}
template<int N> __device__ __forceinline__ void cpa_wait() {
    asm volatile("cp.async.wait_group %0;\n" :: "n"(N));
}

// ---------------------------------------------------------------------------
// fp32 -> tf32-bits conversion (plain + transposing variants)
// ---------------------------------------------------------------------------
__global__ __launch_bounds__(256) void cvt_tf32_kernel(
    const float4* __restrict__ in, float4* __restrict__ out, int n4)
{
    int i = blockIdx.x * 256 + threadIdx.x;
    if (i < n4) {
        float4 v = in[i];
        v.x = __uint_as_float(f2tf(v.x));
        v.y = __uint_as_float(f2tf(v.y));
        v.z = __uint_as_float(f2tf(v.z));
        v.w = __uint_as_float(f2tf(v.w));
        out[i] = v;
    }
}

__global__ __launch_bounds__(256) void cvt_tf32_T(
    const float* __restrict__ in, float* __restrict__ out, int R, int C)
{
    __shared__ float tile[32][33];
    int bx = blockIdx.x * 32, by = blockIdx.y * 32;
    int tx = threadIdx.x & 31, ty = threadIdx.x >> 5;
    #pragma unroll
    for (int i = ty; i < 32; i += 8)
        tile[i][tx] = in[(size_t)(by + i) * C + bx + tx];
    __syncthreads();
    #pragma unroll
    for (int i = ty; i < 32; i += 8)
        out[(size_t)(bx + i) * R + by + tx] = __uint_as_float(f2tf(tile[tx][i]));
}

// ---------------------------------------------------------------------------
// tf32 GEMM, BK=32 (64 HMMA per barrier), ldmatrix + register ping-pong
// fragments, cp.async 3-stage. B is TRANSPOSED [N][K]. Mid-iteration barrier
// fences the cross-iteration fragment prefetch.
// ---------------------------------------------------------------------------
constexpr int GBM = 128, GBN = 128, GBK = 32;
constexpr int TSTR = 36;              // row stride words (32 + 4 pad): conflict-free
constexpr int TTILE = 128 * TSTR;     // 4608 words per tile
constexpr int GEMM_SMEM_B = 6 * TTILE * 4;  // 110592 B (2 CTAs/SM: 221KB)

__global__ __launch_bounds__(256, 2) void tf32_gemm(
    const float* __restrict__ A, const float* __restrict__ BT,
    const float* __restrict__ bias, float* __restrict__ Cout,
    int N, int mode)
{
    extern __shared__ float gsm[];
    float* sA = gsm;                   // [3][TTILE]
    float* sB = gsm + 3 * TTILE;       // [3][TTILE]
    unsigned sAb = (unsigned)__cvta_generic_to_shared(sA);
    unsigned sBb = (unsigned)__cvta_generic_to_shared(sB);
    const int K = CDIM;

    int tid = threadIdx.x;
    int warp = tid >> 5, lane = tid & 31;
    int g = lane >> 2, t = lane & 3;
    int wm = warp >> 1, wn = warp & 1;
    int rowbase = wm * 32, colbase = wn * 64;

    const float* Ablk = A + (size_t)blockIdx.y * GBM * K;
    const float* Bblk = BT + (size_t)blockIdx.x * GBN * K;

    float acc[2][8][4];
    #pragma unroll
    for (int mt = 0; mt < 2; mt++)
        #pragma unroll
        for (int nt = 0; nt < 8; nt++)
            #pragma unroll
            for (int r = 0; r < 4; r++) acc[mt][nt][r] = 0.f;

    // per-thread load slots: 128 rows x 8 chunks (16B) = 1024 slots, 4/thread/tensor
    int cRow[4], cCh[4];
    #pragma unroll
    for (int u = 0; u < 4; u++) {
        int idx = tid + u * 256;
        cRow[u] = idx >> 3; cCh[u] = idx & 7;
    }

    #define LOAD_STAGE(k0, s)                                                     \
        do {                                                                      \
            _Pragma("unroll")                                                     \
            for (int u = 0; u < 4; u++) {                                         \
                cpa16s(sAb + ((s) * TTILE + cRow[u] * TSTR) * 4 + cCh[u] * 16,    \
                       Ablk + (size_t)cRow[u] * K + (k0) + cCh[u] * 4);           \
                cpa16s(sBb + ((s) * TTILE + cRow[u] * TSTR) * 4 + cCh[u] * 16,    \
                       Bblk + (size_t)cRow[u] * K + (k0) + cCh[u] * 4);           \
            }                                                                     \
        } while (0)

    // ldmatrix per-lane byte offsets within a stage (add kk*32 bytes per k-step)
    unsigned aoff = ((rowbase + (lane & 15)) * TSTR + ((lane >> 4) << 2)) * 4;
    unsigned boff = ((colbase + (lane & 7) + ((lane >= 16) ? 8 : 0)) * TSTR
                     + (((lane >> 3) & 1) << 2)) * 4;

    unsigned afr[2][2][4];
    unsigned bfr[2][16];

    #define LDFRAGS(pp, aS, bS, kk)                                               \
        do {                                                                      \
            _Pragma("unroll")                                                     \
            for (int mt = 0; mt < 2; mt++)                                        \
                ldsm4(afr[pp][mt], (aS) + mt * 16 * TSTR * 4 + (kk) * 32);        \
            _Pragma("unroll")                                                     \
            for (int np = 0; np < 4; np++)                                        \
                ldsm4(&bfr[pp][np * 4], (bS) + np * 16 * TSTR * 4 + (kk) * 32);   \
        } while (0)

    #define DOMMA(pp)                                                             \
        do {                                                                      \
            _Pragma("unroll")                                                     \
            for (int mt = 0; mt < 2; mt++)                                        \
                _Pragma("unroll")                                                 \
                for (int nt = 0; nt < 8; nt++)                                    \
                    mma_tf32(acc[mt][nt], afr[pp][mt], &bfr[pp][nt * 2]);         \
        } while (0)

    LOAD_STAGE(0, 0); cpa_commit();
    LOAD_STAGE(GBK, 1); cpa_commit();
    cpa_wait<1>();
    __syncthreads();
    LDFRAGS(0, sAb + aoff, sBb + boff, 0);   // buf0 <- kk0 (fenced above)

    const int NT = K / GBK;  // 24
    for (int it = 0; it < NT; it++) {
        int buf = it % 3, nbuf = (it + 1) % 3;
        if (it + 2 < NT) LOAD_STAGE((it + 2) * GBK, (it + 2) % 3);
        cpa_commit();

        unsigned aC = sAb + buf * TTILE * 4 + aoff;
        unsigned bC = sBb + buf * TTILE * 4 + boff;
        // ping-pong: buffers alternate 0/1 while k-step advances
        LDFRAGS(1, aC, bC, 1); DOMMA(0);   // buf1<-kk1, consume kk0
        LDFRAGS(0, aC, bC, 2); DOMMA(1);   // buf0<-kk2, consume kk1
        LDFRAGS(1, aC, bC, 3); DOMMA(0);   // buf1<-kk3, consume kk2

        if (it + 1 < NT) {
            cpa_wait<1>();             // stage it+1 complete (this thread)
            __syncthreads();           // ... and visible from ALL threads
            unsigned aN = sAb + nbuf * TTILE * 4 + aoff;
            unsigned bN = sBb + nbuf * TTILE * 4 + boff;
            LDFRAGS(0, aN, bN, 0);    // buf0 <- next-iter kk0
        }
        DOMMA(1);                      // consume kk3
    }

    int mrow0 = blockIdx.y * GBM + rowbase;
    int ncol0 = blockIdx.x * GBN + colbase;

    if (mode == 1) {
        #pragma unroll
        for (int mt = 0; mt < 2; mt++)
            #pragma unroll
            for (int nt = 0; nt < 8; nt++)
                #pragma unroll
                for (int rh = 0; rh < 2; rh++)
                    #pragma unroll
                    for (int cl = 0; cl < 2; cl++) {
                        int row = mrow0 + mt * 16 + g + rh * 8;
                        int col = ncol0 + nt * 8 + 2 * t + cl;
                        Cout[(size_t)row * N + col] = acc[mt][nt][rh * 2 + cl] + bias[col];
                    }
    } else {
        #pragma unroll
        for (int mt = 0; mt < 2; mt++)
            #pragma unroll
            for (int rh = 0; rh < 2; rh++) {
                int m = mrow0 + mt * 16 + g + rh * 8;
                int bb = m / HW, tt = m - bb * HW;
                #pragma unroll
                for (int nt = 0; nt < 8; nt++)
                    #pragma unroll
                    for (int cl = 0; cl < 2; cl++) {
                        int n = ncol0 + nt * 8 + 2 * t + cl;
                        int s = n / CDIM;
                        int rem = n - s * CDIM;
                        int h = rem >> 6, d = rem & 63;
                        g_qkv[(((size_t)s * HEADS + bb * NHEAD + h) * HW + tt) * HD + d]
                            = acc[mt][nt][rh * 2 + cl] + bias[n];
                    }
            }
    }
}

// ---------------------------------------------------------------------------
// Tensor-core attention (round-8 passing version, unchanged)
// ---------------------------------------------------------------------------
constexpr int SSTR   = 204;
constexpr int AK_OFF = 0;
constexpr int AV_OFF = AK_OFF + 200 * 68;
constexpr int AS_OFF = AV_OFF + 200 * 72;
constexpr int AR_OFF = AS_OFF + 112 * SSTR;
constexpr int A_SMEM_W = AR_OFF + 5488;
constexpr int GSTR = 58;

__global__ __launch_bounds__(512) void attn_tc(
    const float* __restrict__ rel_h_tab, const float* __restrict__ rel_w_tab)
{
    extern __shared__ float sm[];
    unsigned* smu = (unsigned*)sm;
    unsigned sbase = (unsigned)__cvta_generic_to_shared(sm);
    float* sK  = sm + AK_OFF;   unsigned* sKu = smu + AK_OFF;
    float* sV  = sm + AV_OFF;   unsigned* sVu = smu + AV_OFF;
    float* sS  = sm + AS_OFF;   unsigned* sSu = smu + AS_OFF;
    float* rel = sm + AR_OFF;   unsigned* sTb = smu + AR_OFF;

    int head = blockIdx.x;
    int tid  = threadIdx.x;
    int warp = tid >> 5, lane = tid & 31;
    int g = lane >> 2, t = lane & 3;

    const float* qg = g_qkv + (size_t)head * HW * HD;
    const float* kg = qg + (size_t)HEADS * HW * HD;
    const float* vg = kg + (size_t)HEADS * HW * HD;

    for (int idx = tid; idx < HW * 16; idx += 512) {
        int r = idx >> 4, c4 = (idx & 15) << 2;
        float4 k = *(const float4*)(kg + r * 64 + c4);
        float4 v = *(const float4*)(vg + r * 64 + c4);
        unsigned* ks = sKu + r * 68 + c4;
        ks[0] = f2tf(k.x); ks[1] = f2tf(k.y); ks[2] = f2tf(k.z); ks[3] = f2tf(k.w);
        unsigned* vs = sVu + r * 72 + c4;
        vs[0] = f2tf(v.x); vs[1] = f2tf(v.y); vs[2] = f2tf(v.z); vs[3] = f2tf(v.w);
    }
    for (int idx = tid; idx < 4 * 72; idx += 512) sV[196 * 72 + idx] = 0.f;
    for (int idx = tid; idx < 4 * 68; idx += 512) sK[196 * 68 + idx] = 0.f;
    for (int idx = tid; idx < 56 * 64; idx += 512) {
        int j = idx >> 6, d = idx & 63;
        float v = (j < 27) ? rel_h_tab[j * 64 + d]
                 : (j < 54) ? rel_w_tab[(j - 27) * 64 + d] : 0.f;
        sTb[j * 68 + d] = f2tf(v);
    }
    __syncthreads();

    if (warp < 13) {
        int r0 = warp * 16;
        unsigned qf[8][4];
        #pragma unroll
        for (int ks = 0; ks < 8; ks++) {
            qf[ks][0] = f2tf(qg[(r0 + g) * 64 + ks * 8 + t]);
            qf[ks][1] = f2tf(qg[(r0 + g + 8) * 64 + ks * 8 + t]);
            qf[ks][2] = f2tf(qg[(r0 + g) * 64 + ks * 8 + t + 4]);
            qf[ks][3] = f2tf(qg[(r0 + g + 8) * 64 + ks * 8 + t + 4]);
        }
        unsigned tb = sbase + (AR_OFF + (lane & 7) * 68 + (lane >> 3) * 4) * 4;
        #pragma unroll
        for (int n0 = 0; n0 < 7; n0++) {
            unsigned tfr[16];
            #pragma unroll
            for (int j = 0; j < 4; j++)
                ldsm4(&tfr[4 * j], tb + (n0 * 8 * 68 + j * 16) * 4);
            float c4a[4] = {0.f, 0.f, 0.f, 0.f};
            float c4b[4] = {0.f, 0.f, 0.f, 0.f};
            #pragma unroll
            for (int ks = 0; ks < 4; ks++) mma_tf32(c4a, qf[ks], &tfr[2 * ks]);
            #pragma unroll
            for (int ks = 4; ks < 8; ks++) mma_tf32(c4b, qf[ks], &tfr[2 * ks]);
            #pragma unroll
            for (int r = 0; r < 4; r++) c4a[r] += c4b[r];
            *(float2*)&sS[(r0 + g) * GSTR + n0 * 8 + 2 * t]     = make_float2(c4a[0], c4a[1]);
            *(float2*)&sS[(r0 + g + 8) * GSTR + n0 * 8 + 2 * t] = make_float2(c4a[2], c4a[3]);
        }
    }
    __syncthreads();

    for (int idx = tid; idx < 5488; idx += 512) {
        int row = idx / 28, c = idx - row * 28;
        if (c < 14)
            rel[row * 14 + c] = sS[row * GSTR + (row / 14 - c + 13)];
        else
            rel[2744 + row * 14 + (c - 14)] = sS[row * GSTR + 27 + (row % 14) - (c - 14) + 13];
    }
    __syncthreads();

    int bb = head / NHEAD, hh = head - bb * NHEAD;
    float* outp = g_att + (size_t)bb * HW * CDIM + hh * HD;
    const float scale = 0.125f;

    #pragma unroll
    for (int blk = 0; blk < 2; blk++) {
        int ntiles = (blk == 0) ? 7 : 6;
        bool act = (warp >> 1) < ntiles;
        int mt  = blk * 7 + (warp >> 1);
        int lr0 = (warp >> 1) * 16;
        int half = warp & 1;

        unsigned qf[8][4];
        if (act) {
            int r0 = mt * 16;
            #pragma unroll
            for (int ks = 0; ks < 8; ks++) {
                qf[ks][0] = f2tf(qg[(r0 + g) * 64 + ks * 8 + t]);
                qf[ks][1] = f2tf(qg[(r0 + g + 8) * 64 + ks * 8 + t]);
                qf[ks][2] = f2tf(qg[(r0 + g) * 64 + ks * 8 + t + 4]);
                qf[ks][3] = f2tf(qg[(r0 + g + 8) * 64 + ks * 8 + t + 4]);
            }
        }

        if (act) {
            unsigned kb = sbase + ((lane & 7) * 68 + (lane >> 3) * 4) * 4;
            int n0beg = half * 13, n0end = n0beg + 13 - half;
            for (int n0 = n0beg; n0 < n0end; n0++) {
                unsigned kfr[16];
                #pragma unroll
                for (int j = 0; j < 4; j++)
                    ldsm4(&kfr[4 * j], kb + (n0 * 8 * 68 + j * 16) * 4);
                float c4a[4] = {0.f, 0.f, 0.f, 0.f};
                float c4b[4] = {0.f, 0.f, 0.f, 0.f};
                #pragma unroll
                for (int ks = 0; ks < 4; ks++) mma_tf32(c4a, qf[ks], &kfr[2 * ks]);
                #pragma unroll
                for (int ks = 4; ks < 8; ks++) mma_tf32(c4b, qf[ks], &kfr[2 * ks]);
                #pragma unroll
                for (int r = 0; r < 4; r++) c4a[r] += c4b[r];
                *(float2*)&sS[(lr0 + g) * SSTR + n0 * 8 + 2 * t]     = make_float2(c4a[0], c4a[1]);
                *(float2*)&sS[(lr0 + g + 8) * SSTR + n0 * 8 + 2 * t] = make_float2(c4a[2], c4a[3]);
            }
        }
        __syncthreads();

        int nrows = (blk == 0) ? 112 : 84;
        int growb = blk * 112;
        for (int lr = warp; lr < nrows; lr += 16) {
            int grow = growb + lr;
            float vals[7];
            float mx = -1e30f;
            #pragma unroll
            for (int i = 0; i < 7; i++) {
                int j = lane + 32 * i;
                float v;
                if (j < HW)
                    v = fmaf(sS[lr * SSTR + j], scale,
                             rel[grow * 14 + j / 14] + rel[2744 + grow * 14 + j % 14]);
                else v = -1e30f;
                vals[i] = v;
                mx = fmaxf(mx, v);
            }
            #pragma unroll
            for (int off = 16; off; off >>= 1)
                mx = fmaxf(mx, __shfl_xor_sync(0xffffffffu, mx, off));
            float sum = 0.f;
            #pragma unroll
            for (int i = 0; i < 7; i++) {
                int j = lane + 32 * i;
                float e = (j < HW) ? __expf(vals[i] - mx) : 0.f;
                vals[i] = e;
                sum += e;
            }
            #pragma unroll
            for (int off = 16; off; off >>= 1)
                sum += __shfl_xor_sync(0xffffffffu, sum, off);
            float inv = 1.f / sum;
            #pragma unroll
            for (int i = 0; i < 7; i++) {
                int j = lane + 32 * i;
                if (j < HW)        sSu[lr * SSTR + j] = f2tf(vals[i] * inv);
                else if (j < SSTR) sSu[lr * SSTR + j] = 0u;
            }
        }
        __syncthreads();

        if (act) {
            int ntb = half * 4;
            float oacc[4][4];
            #pragma unroll
            for (int nt = 0; nt < 4; nt++)
                #pragma unroll
                for (int r = 0; r < 4; r++) oacc[nt][r] = 0.f;

            unsigned pb = sbase + (AS_OFF + (lr0 + (lane & 15)) * SSTR
                                   + ((lane >= 16) ? 4 : 0)) * 4;
            unsigned aP[2][4];
            ldsm4(aP[0], pb);
            for (int ks = 0; ks < 25; ks++) {
                int cur = ks & 1;
                if (ks < 24) ldsm4(aP[cur ^ 1], pb + (ks + 1) * 32);
                #pragma unroll
                for (int nt = 0; nt < 4; nt++) {
                    unsigned bfr2[2];
                    bfr2[0] = sVu[(ks * 8 + t) * 72 + (ntb + nt) * 8 + g];
                    bfr2[1] = sVu[(ks * 8 + t + 4) * 72 + (ntb + nt) * 8 + g];
                    mma_tf32(oacc[nt], aP[cur], bfr2);
                }
            }
            #pragma unroll
            for (int rh = 0; rh < 2; rh++) {
                int row = mt * 16 + g + rh * 8;
                if (row < HW) {
                    #pragma unroll
                    for (int nt = 0; nt < 4; nt++) {
                        float2 w;
                        w.x = __uint_as_float(f2tf(oacc[nt][rh * 2]));
                        w.y = __uint_as_float(f2tf(oacc[nt][rh * 2 + 1]));
                        *(float2*)&outp[(size_t)row * CDIM + (ntb + nt) * 8 + 2 * t] = w;
                    }
                }
            }
        }
        __syncthreads();
    }
}

// ---------------------------------------------------------------------------
extern "C" void kernel_launch(void* const* d_in, const int* in_sizes, int n_in,
                              void* d_out, int out_size)
{
    const float* hidden = (const float*)d_in[0];
    const float* w_qkv  = (const float*)d_in[1];
    const float* b_qkv  = (const float*)d_in[2];
    const float* rph    = (const float*)d_in[3];
    const float* rpw    = (const float*)d_in[4];
    const float* w_proj = (const float*)d_in[5];
    const float* b_proj = (const float*)d_in[6];
    float* out = (float*)d_out;

    (void)in_sizes; (void)n_in; (void)out_size;

    cudaFuncSetAttribute(attn_tc, cudaFuncAttributeMaxDynamicSharedMemorySize,
                         A_SMEM_W * (int)sizeof(float));
    cudaFuncSetAttribute(tf32_gemm, cudaFuncAttributeMaxDynamicSharedMemorySize,
                         GEMM_SMEM_B);

    float *p_hid_tf, *p_wqkv_tf, *p_wproj_tf, *p_att;
    cudaGetSymbolAddress((void**)&p_hid_tf,   g_hid_tf);
    cudaGetSymbolAddress((void**)&p_wqkv_tf,  g_wqkv_tf);
    cudaGetSymbolAddress((void**)&p_wproj_tf, g_wproj_tf);
    cudaGetSymbolAddress((void**)&p_att,      g_att);

    // 0) pre-convert: hidden (plain), weights (transposed to [N][K])
    int n4h = M_ROWS * CDIM / 4;
    cvt_tf32_kernel<<<(n4h + 255) / 256, 256>>>((const float4*)hidden, (float4*)p_hid_tf, n4h);
    cvt_tf32_T<<<dim3(3 * CDIM / 32, CDIM / 32), 256>>>(w_qkv, p_wqkv_tf, CDIM, 3 * CDIM);
    cvt_tf32_T<<<dim3(CDIM / 32, CDIM / 32), 256>>>(w_proj, p_wproj_tf, CDIM, CDIM);

    // 1) QKV GEMM + bias + scatter
    dim3 gq(3 * CDIM / GBN, M_ROWS / GBM);   // (18, 196)
    tf32_gemm<<<gq, 256, GEMM_SMEM_B>>>(p_hid_tf, p_wqkv_tf, b_qkv, nullptr, 3 * CDIM, 0);

    // 2) Tensor-core fused attention (writes g_att as tf32 bits)
    attn_tc<<<HEADS, 512, A_SMEM_W * (int)sizeof(float)>>>(rph, rpw);

    // 3) Output projection + bias
    dim3 gp(CDIM / GBN, M_ROWS / GBM);       // (6, 196)
    tf32_gemm<<<gp, 256, GEMM_SMEM_B>>>(p_att, p_wproj_tf, b_proj, out, CDIM, 1);
}

// round 16
// speedup vs baseline: 3.9192x; 1.0814x over previous
#include <cuda_runtime.h>
#include <cstdint>
#include <math.h>

// Problem constants
#define HW     196
#define CDIM   768
#define BATCH  128
#define NHEAD  12
#define HEADS  (BATCH * NHEAD)   // 1536
#define HD     64
#define M_ROWS (BATCH * HW)      // 25088

// Scratch
__device__ float g_qkv[(size_t)3 * HEADS * HW * HD];   // [s][head][t][d] (tf32 bits)
__device__ float g_att[(size_t)M_ROWS * CDIM];         // attn out (tf32 bits)
__device__ float g_hid_tf[(size_t)M_ROWS * CDIM];      // hidden, tf32 bits
__device__ float g_wqkv_tf[(size_t)3 * CDIM * CDIM];   // w_qkv TRANSPOSED [3C][C], tf32
__device__ float g_wproj_tf[(size_t)CDIM * CDIM];      // w_proj TRANSPOSED [C][C], tf32
__device__ float g_tab_tf[56 * 64];                    // [relH(27)|relW(27)|zeros(2)] x 64, tf32

__device__ __forceinline__ unsigned f2tf(float x) {
    unsigned r;
    asm("cvt.rna.tf32.f32 %0, %1;" : "=r"(r) : "f"(x));
    return r;
}

__device__ __forceinline__ void mma_tf32(float c[4], const unsigned a[4], const unsigned* b) {
    asm volatile(
        "mma.sync.aligned.m16n8k8.row.col.f32.tf32.tf32.f32 "
        "{%0,%1,%2,%3},{%4,%5,%6,%7},{%8,%9},{%0,%1,%2,%3};\n"
        : "+f"(c[0]), "+f"(c[1]), "+f"(c[2]), "+f"(c[3])
        : "r"(a[0]), "r"(a[1]), "r"(a[2]), "r"(a[3]), "r"(b[0]), "r"(b[1]));
}

__device__ __forceinline__ void ldsm4(unsigned r[4], unsigned addr) {
    asm volatile("ldmatrix.sync.aligned.m8n8.x4.shared.b16 {%0,%1,%2,%3}, [%4];"
        : "=r"(r[0]), "=r"(r[1]), "=r"(r[2]), "=r"(r[3]) : "r"(addr));
}

__device__ __forceinline__ void cpa16s(uint32_t dst, const float* src) {
    asm volatile("cp.async.cg.shared.global [%0], [%1], 16;\n" :: "r"(dst), "l"(src));
}
__device__ __forceinline__ void cpa_commit() {
    asm volatile("cp.async.commit_group;\n");
}
template<int N> __device__ __forceinline__ void cpa_wait() {
    asm volatile("cp.async.wait_group %0;\n" :: "n"(N));
}

// ---------------------------------------------------------------------------
// fp32 -> tf32-bits conversion kernels
// ---------------------------------------------------------------------------
__global__ __launch_bounds__(256) void cvt_tf32_kernel(
    const float4* __restrict__ in, float4* __restrict__ out, int n4)
{
    int i = blockIdx.x * 256 + threadIdx.x;
    if (i < n4) {
        float4 v = in[i];
        v.x = __uint_as_float(f2tf(v.x));
        v.y = __uint_as_float(f2tf(v.y));
        v.z = __uint_as_float(f2tf(v.z));
        v.w = __uint_as_float(f2tf(v.w));
        out[i] = v;
    }
}

__global__ __launch_bounds__(256) void cvt_tf32_T(
    const float* __restrict__ in, float* __restrict__ out, int R, int C)
{
    __shared__ float tile[32][33];
    int bx = blockIdx.x * 32, by = blockIdx.y * 32;
    int tx = threadIdx.x & 31, ty = threadIdx.x >> 5;
    #pragma unroll
    for (int i = ty; i < 32; i += 8)
        tile[i][tx] = in[(size_t)(by + i) * C + bx + tx];
    __syncthreads();
    #pragma unroll
    for (int i = ty; i < 32; i += 8)
        out[(size_t)(bx + i) * R + by + tx] = __uint_as_float(f2tf(tile[tx][i]));
}

__global__ __launch_bounds__(512) void cvt_tab_kernel(
    const float* __restrict__ rh, const float* __restrict__ rw)
{
    int idx = blockIdx.x * 512 + threadIdx.x;
    if (idx < 56 * 64) {
        int j = idx >> 6, d = idx & 63;
        float v = (j < 27) ? rh[j * 64 + d] : (j < 54) ? rw[(j - 27) * 64 + d] : 0.f;
        g_tab_tf[idx] = __uint_as_float(f2tf(v));
    }
}

// ---------------------------------------------------------------------------
// tf32 GEMM, BK=32, ldmatrix + register ping-pong, cp.async 3-stage.
// mode 0 epilogue writes tf32-rounded bits into g_qkv.
// ---------------------------------------------------------------------------
constexpr int GBM = 128, GBN = 128, GBK = 32;
constexpr int TSTR = 36;
constexpr int TTILE = 128 * TSTR;
constexpr int GEMM_SMEM_B = 6 * TTILE * 4;  // 110592 B

__global__ __launch_bounds__(256, 2) void tf32_gemm(
    const float* __restrict__ A, const float* __restrict__ BT,
    const float* __restrict__ bias, float* __restrict__ Cout,
    int N, int mode)
{
    extern __shared__ float gsm[];
    float* sA = gsm;
    float* sB = gsm + 3 * TTILE;
    unsigned sAb = (unsigned)__cvta_generic_to_shared(sA);
    unsigned sBb = (unsigned)__cvta_generic_to_shared(sB);
    const int K = CDIM;

    int tid = threadIdx.x;
    int warp = tid >> 5, lane = tid & 31;
    int g = lane >> 2, t = lane & 3;
    int wm = warp >> 1, wn = warp & 1;
    int rowbase = wm * 32, colbase = wn * 64;

    const float* Ablk = A + (size_t)blockIdx.y * GBM * K;
    const float* Bblk = BT + (size_t)blockIdx.x * GBN * K;

    float acc[2][8][4];
    #pragma unroll
    for (int mt = 0; mt < 2; mt++)
        #pragma unroll
        for (int nt = 0; nt < 8; nt++)
            #pragma unroll
            for (int r = 0; r < 4; r++) acc[mt][nt][r] = 0.f;

    int cRow[4], cCh[4];
    #pragma unroll
    for (int u = 0; u < 4; u++) {
        int idx = tid + u * 256;
        cRow[u] = idx >> 3; cCh[u] = idx & 7;
    }

    #define LOAD_STAGE(k0, s)                                                     \
        do {                                                                      \
            _Pragma("unroll")                                                     \
            for (int u = 0; u < 4; u++) {                                         \
                cpa16s(sAb + ((s) * TTILE + cRow[u] * TSTR) * 4 + cCh[u] * 16,    \
                       Ablk + (size_t)cRow[u] * K + (k0) + cCh[u] * 4);           \
                cpa16s(sBb + ((s) * TTILE + cRow[u] * TSTR) * 4 + cCh[u] * 16,    \
                       Bblk + (size_t)cRow[u] * K + (k0) + cCh[u] * 4);           \
            }                                                                     \
        } while (0)

    unsigned aoff = ((rowbase + (lane & 15)) * TSTR + ((lane >> 4) << 2)) * 4;
    unsigned boff = ((colbase + (lane & 7) + ((lane >= 16) ? 8 : 0)) * TSTR
                     + (((lane >> 3) & 1) << 2)) * 4;

    unsigned afr[2][2][4];
    unsigned bfr[2][16];

    #define LDFRAGS(pp, aS, bS, kk)                                               \
        do {                                                                      \
            _Pragma("unroll")                                                     \
            for (int mt = 0; mt < 2; mt++)                                        \
                ldsm4(afr[pp][mt], (aS) + mt * 16 * TSTR * 4 + (kk) * 32);        \
            _Pragma("unroll")                                                     \
            for (int np = 0; np < 4; np++)                                        \
                ldsm4(&bfr[pp][np * 4], (bS) + np * 16 * TSTR * 4 + (kk) * 32);   \
        } while (0)

    #define DOMMA(pp)                                                             \
        do {                                                                      \
            _Pragma("unroll")                                                     \
            for (int mt = 0; mt < 2; mt++)                                        \
                _Pragma("unroll")                                                 \
                for (int nt = 0; nt < 8; nt++)                                    \
                    mma_tf32(acc[mt][nt], afr[pp][mt], &bfr[pp][nt * 2]);         \
        } while (0)

    LOAD_STAGE(0, 0); cpa_commit();
    LOAD_STAGE(GBK, 1); cpa_commit();
    cpa_wait<1>();
    __syncthreads();
    LDFRAGS(0, sAb + aoff, sBb + boff, 0);

    const int NT = K / GBK;  // 24
    #pragma unroll 3
    for (int it = 0; it < NT; it++) {
        int buf = it % 3, nbuf = (it + 1) % 3;
        if (it + 2 < NT) LOAD_STAGE((it + 2) * GBK, (it + 2) % 3);
        cpa_commit();

        unsigned aC = sAb + buf * TTILE * 4 + aoff;
        unsigned bC = sBb + buf * TTILE * 4 + boff;
        LDFRAGS(1, aC, bC, 1); DOMMA(0);
        LDFRAGS(0, aC, bC, 2); DOMMA(1);
        LDFRAGS(1, aC, bC, 3); DOMMA(0);

        if (it + 1 < NT) {
            cpa_wait<1>();
            __syncthreads();
            unsigned aN = sAb + nbuf * TTILE * 4 + aoff;
            unsigned bN = sBb + nbuf * TTILE * 4 + boff;
            LDFRAGS(0, aN, bN, 0);
        }
        DOMMA(1);
    }

    int mrow0 = blockIdx.y * GBM + rowbase;
    int ncol0 = blockIdx.x * GBN + colbase;

    if (mode == 1) {
        #pragma unroll
        for (int mt = 0; mt < 2; mt++)
            #pragma unroll
            for (int nt = 0; nt < 8; nt++)
                #pragma unroll
                for (int rh = 0; rh < 2; rh++)
                    #pragma unroll
                    for (int cl = 0; cl < 2; cl++) {
                        int row = mrow0 + mt * 16 + g + rh * 8;
                        int col = ncol0 + nt * 8 + 2 * t + cl;
                        Cout[(size_t)row * N + col] = acc[mt][nt][rh * 2 + cl] + bias[col];
                    }
    } else {
        #pragma unroll
        for (int mt = 0; mt < 2; mt++)
            #pragma unroll
            for (int rh = 0; rh < 2; rh++) {
                int m = mrow0 + mt * 16 + g + rh * 8;
                int bb = m / HW, tt = m - bb * HW;
                #pragma unroll
                for (int nt = 0; nt < 8; nt++)
                    #pragma unroll
                    for (int cl = 0; cl < 2; cl++) {
                        int n = ncol0 + nt * 8 + 2 * t + cl;
                        int s = n / CDIM;
                        int rem = n - s * CDIM;
                        int h = rem >> 6, d = rem & 63;
                        g_qkv[(((size_t)s * HEADS + bb * NHEAD + h) * HW + tt) * HD + d]
                            = __uint_as_float(f2tf(acc[mt][nt][rh * 2 + cl] + bias[n]));
                    }
            }
    }
}

// ---------------------------------------------------------------------------
// Tensor-core attention: cp.async loads (inputs pre-tf32), smem Q staging,
// rel computed by MMA + direct fragment scatter (no gather phase).
// ---------------------------------------------------------------------------
constexpr int SSTR   = 204;
constexpr int AK_OFF = 0;                      // K: 200 x 68
constexpr int AV_OFF = AK_OFF + 200 * 68;      // V: 200 x 72
constexpr int AS_OFF = AV_OFF + 200 * 72;      // S/P 112x204; Q stage 208x68 first
constexpr int AT_OFF = AS_OFF + 208 * 68;      // Tab stage 56x68 (inside S buffer)
constexpr int AR_OFF = AS_OFF + 112 * SSTR;    // rel: 5488
constexpr int A_SMEM_W = AR_OFF + 5488;        // 56336 words = 225344 B

__global__ __launch_bounds__(512) void attn_tc()
{
    extern __shared__ float sm[];
    unsigned* smu = (unsigned*)sm;
    unsigned sbase = (unsigned)__cvta_generic_to_shared(sm);
    float* sK  = sm + AK_OFF;
    float* sV  = sm + AV_OFF;   unsigned* sVu = smu + AV_OFF;
    float* sS  = sm + AS_OFF;   unsigned* sSu = smu + AS_OFF;
    float* rel = sm + AR_OFF;

    int head = blockIdx.x;
    int tid  = threadIdx.x;
    int warp = tid >> 5, lane = tid & 31;
    int g = lane >> 2, t = lane & 3;

    const float* qg = g_qkv + (size_t)head * HW * HD;
    const float* kg = qg + (size_t)HEADS * HW * HD;
    const float* vg = kg + (size_t)HEADS * HW * HD;

    // ---- async loads: K, V, Q, Tab (all already tf32 bits) ----
    for (int idx = tid; idx < HW * 16; idx += 512) {
        int r = idx >> 4, c4 = (idx & 15) << 2;
        cpa16s(sbase + (AK_OFF + r * 68 + c4) * 4, kg + r * 64 + c4);
        cpa16s(sbase + (AV_OFF + r * 72 + c4) * 4, vg + r * 64 + c4);
        cpa16s(sbase + (AS_OFF + r * 68 + c4) * 4, qg + r * 64 + c4);
    }
    for (int idx = tid; idx < 56 * 16; idx += 512) {
        int r = idx >> 4, c4 = (idx & 15) << 2;
        cpa16s(sbase + (AT_OFF + r * 68 + c4) * 4, g_tab_tf + r * 64 + c4);
    }
    cpa_commit();
    // zero pad rows (plain STS, disjoint from cp.async targets)
    for (int idx = tid; idx < 4 * 68; idx += 512)  sK[196 * 68 + idx] = 0.f;
    for (int idx = tid; idx < 4 * 72; idx += 512)  sV[196 * 72 + idx] = 0.f;
    for (int idx = tid; idx < 12 * 68; idx += 512) sS[196 * 68 + idx] = 0.f;  // Q pad rows
    cpa_wait<0>();
    __syncthreads();

    // ---- G = Q @ Tab^T, scatter fragments directly to rel ----
    if (warp < 13) {
        int r0 = warp * 16;
        unsigned qbase = sbase + (AS_OFF + (r0 + (lane & 15)) * 68 + ((lane >> 4) << 2)) * 4;
        unsigned qfg[8][4];
        #pragma unroll
        for (int ks = 0; ks < 8; ks++) ldsm4(qfg[ks], qbase + ks * 32);
        unsigned tb = sbase + (AT_OFF + (lane & 7) * 68 + (lane >> 3) * 4) * 4;
        #pragma unroll
        for (int n0 = 0; n0 < 7; n0++) {
            unsigned tfr[16];
            #pragma unroll
            for (int j = 0; j < 4; j++)
                ldsm4(&tfr[4 * j], tb + (n0 * 8 * 68 + j * 16) * 4);
            float c4a[4] = {0.f, 0.f, 0.f, 0.f};
            float c4b[4] = {0.f, 0.f, 0.f, 0.f};
            #pragma unroll
            for (int ks = 0; ks < 4; ks++) mma_tf32(c4a, qfg[ks], &tfr[2 * ks]);
            #pragma unroll
            for (int ks = 4; ks < 8; ks++) mma_tf32(c4b, qfg[ks], &tfr[2 * ks]);
            #pragma unroll
            for (int e = 0; e < 4; e++) {
                float val = c4a[e] + c4b[e];
                int row = r0 + g + (e >> 1) * 8;
                int col = n0 * 8 + 2 * t + (e & 1);
                if (row < HW) {
                    int ch = row / 14 - col + 13;
                    if (ch >= 0 && ch < 14) rel[row * 14 + ch] = val;
                    int cw = row % 14 - (col - 27) + 13;
                    if (cw >= 0 && cw < 14) rel[2744 + row * 14 + cw] = val;
                }
            }
        }
    }

    // ---- preload Q fragments for both blocks (from smem Q staging) ----
    unsigned qf[2][8][4];
    #pragma unroll
    for (int b = 0; b < 2; b++) {
        int mt = b * 7 + (warp >> 1);
        bool a2 = (warp >> 1) < ((b == 0) ? 7 : 6);
        if (a2) {
            unsigned qb2 = sbase + (AS_OFF + (mt * 16 + (lane & 15)) * 68 + ((lane >> 4) << 2)) * 4;
            #pragma unroll
            for (int ks = 0; ks < 8; ks++) ldsm4(qf[b][ks], qb2 + ks * 32);
        }
    }
    __syncthreads();   // rel scatter + Q reads complete before S overwrites

    int bb = head / NHEAD, hh = head - bb * NHEAD;
    float* outp = g_att + (size_t)bb * HW * CDIM + hh * HD;
    const float scale = 0.125f;

    #pragma unroll
    for (int blk = 0; blk < 2; blk++) {
        int ntiles = (blk == 0) ? 7 : 6;
        bool act = (warp >> 1) < ntiles;
        int mt  = blk * 7 + (warp >> 1);
        int lr0 = (warp >> 1) * 16;
        int half = warp & 1;

        // ---- S = Q K^T ----
        if (act) {
            unsigned kb = sbase + ((lane & 7) * 68 + (lane >> 3) * 4) * 4;
            int n0beg = half * 13, n0end = n0beg + 13 - half;
            for (int n0 = n0beg; n0 < n0end; n0++) {
                unsigned kfr[16];
                #pragma unroll
                for (int j = 0; j < 4; j++)
                    ldsm4(&kfr[4 * j], kb + (n0 * 8 * 68 + j * 16) * 4);
                float c4a[4] = {0.f, 0.f, 0.f, 0.f};
                float c4b[4] = {0.f, 0.f, 0.f, 0.f};
                #pragma unroll
                for (int ks = 0; ks < 4; ks++) mma_tf32(c4a, qf[blk][ks], &kfr[2 * ks]);
                #pragma unroll
                for (int ks = 4; ks < 8; ks++) mma_tf32(c4b, qf[blk][ks], &kfr[2 * ks]);
                #pragma unroll
                for (int r = 0; r < 4; r++) c4a[r] += c4b[r];
                *(float2*)&sS[(lr0 + g) * SSTR + n0 * 8 + 2 * t]     = make_float2(c4a[0], c4a[1]);
                *(float2*)&sS[(lr0 + g + 8) * SSTR + n0 * 8 + 2 * t] = make_float2(c4a[2], c4a[3]);
            }
        }
        __syncthreads();

        // ---- softmax rows ----
        int nrows = (blk == 0) ? 112 : 84;
        int growb = blk * 112;
        for (int lr = warp; lr < nrows; lr += 16) {
            int grow = growb + lr;
            float vals[7];
            float mx = -1e30f;
            #pragma unroll
            for (int i = 0; i < 7; i++) {
                int j = lane + 32 * i;
                float v;
                if (j < HW)
                    v = fmaf(sS[lr * SSTR + j], scale,
                             rel[grow * 14 + j / 14] + rel[2744 + grow * 14 + j % 14]);
                else v = -1e30f;
                vals[i] = v;
                mx = fmaxf(mx, v);
            }
            #pragma unroll
            for (int off = 16; off; off >>= 1)
                mx = fmaxf(mx, __shfl_xor_sync(0xffffffffu, mx, off));
            float sum = 0.f;
            #pragma unroll
            for (int i = 0; i < 7; i++) {
                int j = lane + 32 * i;
                float e = (j < HW) ? __expf(vals[i] - mx) : 0.f;
                vals[i] = e;
                sum += e;
            }
            #pragma unroll
            for (int off = 16; off; off >>= 1)
                sum += __shfl_xor_sync(0xffffffffu, sum, off);
            float inv = 1.f / sum;
            #pragma unroll
            for (int i = 0; i < 7; i++) {
                int j = lane + 32 * i;
                if (j < HW)        sSu[lr * SSTR + j] = f2tf(vals[i] * inv);
                else if (j < SSTR) sSu[lr * SSTR + j] = 0u;
            }
        }
        __syncthreads();

        // ---- O = P V ----
        if (act) {
            int ntb = half * 4;
            float oacc[4][4];
            #pragma unroll
            for (int nt = 0; nt < 4; nt++)
                #pragma unroll
                for (int r = 0; r < 4; r++) oacc[nt][r] = 0.f;

            unsigned pb = sbase + (AS_OFF + (lr0 + (lane & 15)) * SSTR
                                   + ((lane >= 16) ? 4 : 0)) * 4;
            unsigned aP[2][4];
            ldsm4(aP[0], pb);
            for (int ks = 0; ks < 25; ks++) {
                int cur = ks & 1;
                if (ks < 24) ldsm4(aP[cur ^ 1], pb + (ks + 1) * 32);
                #pragma unroll
                for (int nt = 0; nt < 4; nt++) {
                    unsigned bfr2[2];
                    bfr2[0] = sVu[(ks * 8 + t) * 72 + (ntb + nt) * 8 + g];
                    bfr2[1] = sVu[(ks * 8 + t + 4) * 72 + (ntb + nt) * 8 + g];
                    mma_tf32(oacc[nt], aP[cur], bfr2);
                }
            }
            #pragma unroll
            for (int rh = 0; rh < 2; rh++) {
                int row = mt * 16 + g + rh * 8;
                if (row < HW) {
                    #pragma unroll
                    for (int nt = 0; nt < 4; nt++) {
                        float2 w;
                        w.x = __uint_as_float(f2tf(oacc[nt][rh * 2]));
                        w.y = __uint_as_float(f2tf(oacc[nt][rh * 2 + 1]));
                        *(float2*)&outp[(size_t)row * CDIM + (ntb + nt) * 8 + 2 * t] = w;
                    }
                }
            }
        }
        __syncthreads();
    }
}

// ---------------------------------------------------------------------------
extern "C" void kernel_launch(void* const* d_in, const int* in_sizes, int n_in,
                              void* d_out, int out_size)
{
    const float* hidden = (const float*)d_in[0];
    const float* w_qkv  = (const float*)d_in[1];
    const float* b_qkv  = (const float*)d_in[2];
    const float* rph    = (const float*)d_in[3];
    const float* rpw    = (const float*)d_in[4];
    const float* w_proj = (const float*)d_in[5];
    const float* b_proj = (const float*)d_in[6];
    float* out = (float*)d_out;

    (void)in_sizes; (void)n_in; (void)out_size;

    cudaFuncSetAttribute(attn_tc, cudaFuncAttributeMaxDynamicSharedMemorySize,
                         A_SMEM_W * (int)sizeof(float));
    cudaFuncSetAttribute(tf32_gemm, cudaFuncAttributeMaxDynamicSharedMemorySize,
                         GEMM_SMEM_B);

    float *p_hid_tf, *p_wqkv_tf, *p_wproj_tf, *p_att;
    cudaGetSymbolAddress((void**)&p_hid_tf,   g_hid_tf);
    cudaGetSymbolAddress((void**)&p_wqkv_tf,  g_wqkv_tf);
    cudaGetSymbolAddress((void**)&p_wproj_tf, g_wproj_tf);
    cudaGetSymbolAddress((void**)&p_att,      g_att);

    // 0) pre-convert: hidden (plain), weights (transposed), rel tables
    int n4h = M_ROWS * CDIM / 4;
    cvt_tf32_kernel<<<(n4h + 255) / 256, 256>>>((const float4*)hidden, (float4*)p_hid_tf, n4h);
    cvt_tf32_T<<<dim3(3 * CDIM / 32, CDIM / 32), 256>>>(w_qkv, p_wqkv_tf, CDIM, 3 * CDIM);
    cvt_tf32_T<<<dim3(CDIM / 32, CDIM / 32), 256>>>(w_proj, p_wproj_tf, CDIM, CDIM);
    cvt_tab_kernel<<<7, 512>>>(rph, rpw);

    // 1) QKV GEMM + bias + tf32-rounded scatter
    dim3 gq(3 * CDIM / GBN, M_ROWS / GBM);   // (18, 196)
    tf32_gemm<<<gq, 256, GEMM_SMEM_B>>>(p_hid_tf, p_wqkv_tf, b_qkv, nullptr, 3 * CDIM, 0);

    // 2) Tensor-core fused attention
    attn_tc<<<HEADS, 512, A_SMEM_W * (int)sizeof(float)>>>();

    // 3) Output projection + bias
    dim3 gp(CDIM / GBN, M_ROWS / GBM);       // (6, 196)
    tf32_gemm<<<gp, 256, GEMM_SMEM_B>>>(p_att, p_wproj_tf, b_proj, out, CDIM, 1);
}